// round 9
// baseline (speedup 1.0000x reference)
#include <cuda_runtime.h>
#include <cuda_fp16.h>
#include <math.h>
#include <stdint.h>

// ---------------- problem constants ----------------
#define BSZ   512
#define SEQ   3
#define DM    1550
#define DMP   1600          // DM padded to x64
#define DS    16
#define ED    3100
#define EDP   3136          // ED padded to x64
#define DTR   97
#define DTKP  128           // dt GEMM K padded
#define DBCN  129
#define DBCP  132           // fp32 dbc ldc
#define VOC   128
#define NR    (BSZ*SEQ)
#define OE    256
#define EPSF  1e-5f

#define SROW  72            // smem row stride in halves (BK=64 + 8 pad)
#define NSTG  3             // pipeline stages

// ---------------- fp32 scratch ----------------
__device__ __align__(256) float g_h    [NR*DM];
__device__ __align__(256) float g_xz   [NR*2*ED];
__device__ __align__(256) float g_xc   [NR*ED];
__device__ __align__(256) float g_dbc  [NR*DBCP];
__device__ __align__(256) float g_delta[NR*ED];
__device__ __align__(256) float g_negA [2*ED*DS];
__device__ __align__(256) float g_logit[NR*VOC];
__device__ __align__(256) float g_t    [NR*OE];
__device__ float g_part [384];
__device__ float g_stats[2];
__device__ float g_wesum[OE];

// ---------------- fp16 GEMM operand scratch (zero-init pads) ----------------
__device__ __align__(256) __half h_xn  [NR*DMP];
__device__ __align__(256) __half h_inw [2*2*ED*DMP];
__device__ __align__(256) __half h_xct [NR*EDP];
__device__ __align__(256) __half h_xpw [2*DBCN*EDP];
__device__ __align__(256) __half h_dbc [NR*DTKP];
__device__ __align__(256) __half h_dtw [2*ED*DTKP];
__device__ __align__(256) __half h_ys  [NR*EDP];
__device__ __align__(256) __half h_outw[2*DM*EDP];
__device__ __align__(256) __half h_lmw [VOC*DMP];
__device__ __align__(256) __half h_nrm [NR*VOC];
__device__ __align__(256) __half h_embw[OE*VOC];

__device__ __forceinline__ float siluf(float v){ return v / (1.f + expf(-v)); }

__device__ __forceinline__ void mma_f16(float c[4],
    uint32_t a0, uint32_t a1, uint32_t a2, uint32_t a3,
    uint32_t b0, uint32_t b1)
{
    asm volatile(
        "mma.sync.aligned.m16n8k16.row.col.f32.f16.f16.f32 "
        "{%0,%1,%2,%3}, {%4,%5,%6,%7}, {%8,%9}, {%0,%1,%2,%3};"
        : "+f"(c[0]), "+f"(c[1]), "+f"(c[2]), "+f"(c[3])
        : "r"(a0), "r"(a1), "r"(a2), "r"(a3), "r"(b0), "r"(b1));
}

__device__ __forceinline__ void cpa16(uint32_t sdst, const __half* gsrc, int nbytes){
    asm volatile("cp.async.cg.shared.global [%0], [%1], 16, %2;"
                 :: "r"(sdst), "l"(gsrc), "r"(nbytes));
}

__device__ __forceinline__ void ldsm4(uint32_t r[4], uint32_t addr){
    asm volatile("ldmatrix.sync.aligned.m8n8.x4.shared.b16 {%0,%1,%2,%3}, [%4];"
        : "=r"(r[0]), "=r"(r[1]), "=r"(r[2]), "=r"(r[3]) : "r"(addr));
}

// ============ k_hmma256: CTA 256x128, 8 warps 4x2, warp tile 64x64 ============
// C[M,N] (op)= A[M,K] * B[N,K]^T. Requirements: M % 256 == 0; K % 64 == 0, K>=128.
// mode 0: C = acc ; 1: C += acc.
__global__ void __launch_bounds__(256, 1) k_hmma256(
    const __half* __restrict__ A, int lda,
    const __half* __restrict__ B, int ldb,
    float* __restrict__ C, int ldc,
    int M, int N, int K, int mode)
{
    extern __shared__ __half smh[];
    __half* As = smh;                       // [NSTG][256][SROW]
    __half* Bs = smh + NSTG*256*SROW;       // [NSTG][128][SROW]

    const int tid  = threadIdx.x;
    const int wid  = tid >> 5, lane = tid & 31;
    const int g    = lane >> 2, tg = lane & 3;
    const int wm   = (wid >> 1) * 64;       // 4 warp-rows
    const int wn   = (wid & 1) * 64;        // 2 warp-cols
    const int bm   = blockIdx.y * 256;
    const int bn   = blockIdx.x * 128;
    const int lrow = tid >> 3;              // 0..31
    const int lcol = (tid & 7) * 8;

    const uint32_t sA = (uint32_t)__cvta_generic_to_shared(As);
    const uint32_t sB = (uint32_t)__cvta_generic_to_shared(Bs);

    uint32_t aaddr[4], baddr[4];
    {
        int arow = wm + (lane & 15);
        int acol = ((lane >> 4) & 1) * 8;
        #pragma unroll
        for (int mt = 0; mt < 4; mt++)
            aaddr[mt] = sA + (uint32_t)(((arow + mt*16)*SROW + acol)*2);
        #pragma unroll
        for (int ntp = 0; ntp < 4; ntp++){
            int brow = wn + ntp*16 + (lane & 7) + ((lane >> 4) & 1)*8;
            int bcol = ((lane >> 3) & 1) * 8;
            baddr[ntp] = sB + (uint32_t)((brow*SROW + bcol)*2);
        }
    }

    float acc[4][8][4];
    #pragma unroll
    for (int mt = 0; mt < 4; mt++)
        #pragma unroll
        for (int nt = 0; nt < 8; nt++)
            #pragma unroll
            for (int i = 0; i < 4; i++) acc[mt][nt][i] = 0.f;

    const int nch = K >> 6;

    auto issue = [&](int c){
        const int gk = c*64 + lcol;
        const int s  = c % NSTG;
        uint32_t da = sA + (uint32_t)((s*256*SROW + lrow*SROW + lcol)*2);
        #pragma unroll
        for (int p = 0; p < 8; p++)
            cpa16(da + (uint32_t)(p*32*SROW*2),
                  A + (size_t)(bm + lrow + p*32)*lda + gk, 16);
        uint32_t db = sB + (uint32_t)((s*128*SROW + lrow*SROW + lcol)*2);
        #pragma unroll
        for (int p = 0; p < 4; p++){
            int gn = bn + lrow + p*32;
            cpa16(db + (uint32_t)(p*32*SROW*2),
                  B + (size_t)(gn < N ? gn : 0)*ldb + gk, (gn < N) ? 16 : 0);
        }
        asm volatile("cp.async.commit_group;");
    };

    issue(0);
    issue(1);
    for (int c = 0; c < nch; c++){
        if (c + 1 < nch) asm volatile("cp.async.wait_group 1;");
        else             asm volatile("cp.async.wait_group 0;");
        __syncthreads();
        if (c + 2 < nch) issue(c + 2);

        const uint32_t offA = (uint32_t)((c % NSTG)*256*SROW*2);
        const uint32_t offB = (uint32_t)((c % NSTG)*128*SROW*2);
        #pragma unroll
        for (int kst = 0; kst < 4; kst++){
            uint32_t af[4][4], bfr[4][4];
            #pragma unroll
            for (int mt = 0; mt < 4; mt++)
                ldsm4(af[mt], aaddr[mt] + offA + kst*32);
            #pragma unroll
            for (int ntp = 0; ntp < 4; ntp++)
                ldsm4(bfr[ntp], baddr[ntp] + offB + kst*32);
            #pragma unroll
            for (int mt = 0; mt < 4; mt++)
                #pragma unroll
                for (int nt = 0; nt < 8; nt++)
                    mma_f16(acc[mt][nt],
                            af[mt][0], af[mt][1], af[mt][2], af[mt][3],
                            bfr[nt >> 1][(nt & 1)*2], bfr[nt >> 1][(nt & 1)*2 + 1]);
        }
    }

    #pragma unroll
    for (int mt = 0; mt < 4; mt++){
        int r0 = bm + wm + mt*16 + g;
        #pragma unroll
        for (int nt = 0; nt < 8; nt++){
            int cl = bn + wn + nt*8 + 2*tg;
            #pragma unroll
            for (int i = 0; i < 4; i++){
                int rr = r0 + (i >> 1)*8;
                int cc = cl + (i & 1);
                if (cc >= N) continue;
                float v = acc[mt][nt][i];
                size_t idx = (size_t)rr*ldc + cc;
                if (mode == 1) v += C[idx];
                C[idx] = v;
            }
        }
    }
}
#define SMEM256 (NSTG*(256+128)*SROW*sizeof(__half))   // 165888

// ---------------- k_hmma: 8-warp 2x4 kernel (small GEMMs), unchanged ----------------
// mode 0: C = acc ; 2: softplus(acc+bias) ; 3: C = acc AND Ch = half(acc) for c<DTR.
template<int MT>
__global__ void __launch_bounds__(256, 2) k_hmma(
    const __half* __restrict__ A, int lda,
    const __half* __restrict__ B, int ldb,
    float* __restrict__ C, int ldc,
    int M, int N, int K,
    int mode, const float* __restrict__ bias,
    __half* __restrict__ Ch, int ldch)
{
    constexpr int BM = MT*32;
    extern __shared__ __half smh[];
    __half* As = smh;
    __half* Bs = smh + NSTG*BM*SROW;

    const int tid  = threadIdx.x;
    const int wid  = tid >> 5, lane = tid & 31;
    const int g    = lane >> 2, tg = lane & 3;
    const int wm   = (wid >> 2) * (MT*16);
    const int wn   = (wid & 3) * 32;
    const int bm   = blockIdx.y * BM;
    const int bn   = blockIdx.x * 128;
    const int lrow = tid >> 3;
    const int lcol = (tid & 7) * 8;

    const uint32_t sA = (uint32_t)__cvta_generic_to_shared(As);
    const uint32_t sB = (uint32_t)__cvta_generic_to_shared(Bs);

    uint32_t aaddr[MT], baddr[2];
    {
        int arow = wm + (lane & 15);
        int acol = ((lane >> 4) & 1) * 8;
        #pragma unroll
        for (int mt = 0; mt < MT; mt++)
            aaddr[mt] = sA + (uint32_t)(((arow + mt*16)*SROW + acol)*2);
        #pragma unroll
        for (int ntp = 0; ntp < 2; ntp++){
            int brow = wn + ntp*16 + (lane & 7) + ((lane >> 4) & 1)*8;
            int bcol = ((lane >> 3) & 1) * 8;
            baddr[ntp] = sB + (uint32_t)((brow*SROW + bcol)*2);
        }
    }

    float acc[MT][4][4];
    #pragma unroll
    for (int mt = 0; mt < MT; mt++)
        #pragma unroll
        for (int nt = 0; nt < 4; nt++)
            #pragma unroll
            for (int i = 0; i < 4; i++) acc[mt][nt][i] = 0.f;

    const int nch = K >> 6;

    auto issue = [&](int c){
        const int gk = c*64 + lcol;
        const int s  = c % NSTG;
        uint32_t da = sA + (uint32_t)((s*BM*SROW + lrow*SROW + lcol)*2);
        #pragma unroll
        for (int p = 0; p < BM/32; p++)
            cpa16(da + (uint32_t)(p*32*SROW*2),
                  A + (size_t)(bm + lrow + p*32)*lda + gk, 16);
        uint32_t db = sB + (uint32_t)((s*128*SROW + lrow*SROW + lcol)*2);
        #pragma unroll
        for (int p = 0; p < 4; p++){
            int gn = bn + lrow + p*32;
            cpa16(db + (uint32_t)(p*32*SROW*2),
                  B + (size_t)(gn < N ? gn : 0)*ldb + gk, (gn < N) ? 16 : 0);
        }
        asm volatile("cp.async.commit_group;");
    };

    issue(0);
    issue(1);
    for (int c = 0; c < nch; c++){
        if (c + 1 < nch) asm volatile("cp.async.wait_group 1;");
        else             asm volatile("cp.async.wait_group 0;");
        __syncthreads();
        if (c + 2 < nch) issue(c + 2);

        const uint32_t offA = (uint32_t)((c % NSTG)*BM*SROW*2);
        const uint32_t offB = (uint32_t)((c % NSTG)*128*SROW*2);
        #pragma unroll
        for (int kst = 0; kst < 4; kst++){
            uint32_t af[MT][4], bfr[2][4];
            #pragma unroll
            for (int mt = 0; mt < MT; mt++)
                ldsm4(af[mt], aaddr[mt] + offA + kst*32);
            #pragma unroll
            for (int ntp = 0; ntp < 2; ntp++)
                ldsm4(bfr[ntp], baddr[ntp] + offB + kst*32);
            #pragma unroll
            for (int mt = 0; mt < MT; mt++)
                #pragma unroll
                for (int nt = 0; nt < 4; nt++)
                    mma_f16(acc[mt][nt],
                            af[mt][0], af[mt][1], af[mt][2], af[mt][3],
                            bfr[nt >> 1][(nt & 1)*2], bfr[nt >> 1][(nt & 1)*2 + 1]);
        }
    }

    #pragma unroll
    for (int mt = 0; mt < MT; mt++){
        int r0 = bm + wm + mt*16 + g;
        #pragma unroll
        for (int nt = 0; nt < 4; nt++){
            int cl = bn + wn + nt*8 + 2*tg;
            #pragma unroll
            for (int i = 0; i < 4; i++){
                int rr = r0 + (i >> 1)*8;
                int cc = cl + (i & 1);
                if (cc >= N) continue;
                float v = acc[mt][nt][i];
                size_t idx = (size_t)rr*ldc + cc;
                if (mode == 2){
                    float xv = v + bias[cc];
                    v = fmaxf(xv, 0.f) + log1pf(expf(-fabsf(xv)));
                } else if (mode == 3){
                    if (cc < DTR) Ch[(size_t)rr*ldch + cc] = __float2half(v);
                }
                C[idx] = v;
            }
        }
    }
}

#define SMEMH4 (NSTG*(128+128)*SROW*sizeof(__half))   // 110592
#define SMEMH2 (NSTG*(64 +128)*SROW*sizeof(__half))   // 82944

// ---------------- vectorized fp32 -> padded fp16 ----------------
__global__ void k_cvt2(const float* __restrict__ src, __half* __restrict__ dst,
                       int K, int KP){
    int r = blockIdx.x;
    const float2* s = (const float2*)(src + (size_t)r*K);
    __half* d = dst + (size_t)r*KP;
    const int n2 = K >> 1;
    for (int i = threadIdx.x; i < n2; i += blockDim.x){
        float2 v = s[i];
        *(__half2*)(d + 2*i) = __floats2half2_rn(v.x, v.y);
    }
}

__global__ void k_cvtw(const float* __restrict__ src, __half* __restrict__ dst,
                       int K, int KP, int n){
    int i = blockIdx.x*blockDim.x + threadIdx.x;
    if (i < n) dst[(size_t)(i/K)*KP + (i%K)] = __float2half(src[i]);
}

// ---------------- input transpose ----------------
__global__ void k_transpose_in(const float* __restrict__ x){
    int i = blockIdx.x*blockDim.x + threadIdx.x;
    if (i >= NR*DM) return;
    int n = i / DM, d = i % DM;
    int c = d / 25, r = d % 25, f = r / 5, e = r % 5;
    g_h[i] = x[((n*5 + f)*62 + c)*5 + e];
}

// ---------------- rmsnorm: g_h -> h_xn (fp16, padded) ----------------
__global__ void k_rmsnorm(const float* __restrict__ w){
    __shared__ float sh[33];
    int n = blockIdx.x;
    const float* row = g_h + (size_t)n*DM;
    float ss = 0.f;
    for (int d = threadIdx.x; d < DM; d += blockDim.x){ float v = row[d]; ss += v*v; }
    for (int o = 16; o; o >>= 1) ss += __shfl_down_sync(0xffffffffu, ss, o);
    if ((threadIdx.x & 31) == 0) sh[threadIdx.x >> 5] = ss;
    __syncthreads();
    if (threadIdx.x < 32){
        float v = (threadIdx.x < (int)(blockDim.x >> 5)) ? sh[threadIdx.x] : 0.f;
        for (int o = 16; o; o >>= 1) v += __shfl_down_sync(0xffffffffu, v, o);
        if (threadIdx.x == 0) sh[32] = rsqrtf(v / (float)DM + EPSF);
    }
    __syncthreads();
    float sc = sh[32];
    for (int d = threadIdx.x; d < DM; d += blockDim.x)
        h_xn[(size_t)n*DMP + d] = __float2half(row[d] * sc * w[d]);
}

// ---------------- depthwise causal conv + silu ----------------
__global__ void k_conv_silu(const float* __restrict__ cw, const float* __restrict__ cb){
    int e = blockIdx.x*blockDim.x + threadIdx.x;
    int b = blockIdx.y;
    if (e >= ED) return;
    size_t r0 = (size_t)(b*SEQ + 0)*(2*ED);
    size_t r1 = (size_t)(b*SEQ + 1)*(2*ED);
    size_t r2 = (size_t)(b*SEQ + 2)*(2*ED);
    float x0 = g_xz[r0 + e], x1 = g_xz[r1 + e], x2 = g_xz[r2 + e];
    float w1 = cw[e*4+1], w2 = cw[e*4+2], w3 = cw[e*4+3];
    float bb = cb[e];
    float y0 = siluf(bb + w3*x0);
    float y1 = siluf(bb + w2*x0 + w3*x1);
    float y2 = siluf(bb + w1*x0 + w2*x1 + w3*x2);
    g_xc[(size_t)(b*SEQ + 0)*ED + e] = y0;  h_xct[(size_t)(b*SEQ + 0)*EDP + e] = __float2half(y0);
    g_xc[(size_t)(b*SEQ + 1)*ED + e] = y1;  h_xct[(size_t)(b*SEQ + 1)*EDP + e] = __float2half(y1);
    g_xc[(size_t)(b*SEQ + 2)*ED + e] = y2;  h_xct[(size_t)(b*SEQ + 2)*EDP + e] = __float2half(y2);
}

// ---------------- negA (both layers) ----------------
__global__ void k_negA(const float* __restrict__ Alog){
    int i = blockIdx.x*blockDim.x + threadIdx.x;
    if (i < 2*ED*DS) g_negA[i] = -expf(Alog[i]);
}

// ---------------- fused SSM scan: block = e-slice, loops 16 batches ----------------
#define SCAN_BB 16
__global__ void k_scan(const float* __restrict__ nAbase, const float* __restrict__ Dp){
    __shared__ float sB[SEQ][DS], sC[SEQ][DS];
    int e = blockIdx.x*blockDim.x + threadIdx.x;
    int t = threadIdx.x;
    bool act = (e < ED);

    float nA[DS], dpe = 0.f;
    if (act){
        #pragma unroll
        for (int n = 0; n < DS; n++) nA[n] = nAbase[e*DS + n];
        dpe = Dp[e];
    }

    for (int bb = 0; bb < SCAN_BB; bb++){
        int b = blockIdx.y*SCAN_BB + bb;
        if (t < SEQ*DS){
            int s = t / DS, n = t % DS;
            size_t base = (size_t)(b*SEQ + s)*DBCP + DTR;
            sB[s][n] = g_dbc[base + n];
            sC[s][n] = g_dbc[base + DS + n];
        }
        __syncthreads();
        if (act){
            float hst[DS];
            #pragma unroll
            for (int n = 0; n < DS; n++) hst[n] = 0.f;
            #pragma unroll
            for (int s = 0; s < SEQ; s++){
                size_t row = (size_t)(b*SEQ + s);
                float d   = g_delta[row*ED + e];
                float xcv = g_xc[row*ED + e];
                float dx  = d * xcv;
                float y = 0.f;
                #pragma unroll
                for (int n = 0; n < DS; n++){
                    float dA = __expf(d * nA[n]);
                    hst[n] = dA*hst[n] + dx*sB[s][n];
                    y = fmaf(hst[n], sC[s][n], y);
                }
                y += dpe * xcv;
                float z = g_xz[row*(2*ED) + ED + e];
                h_ys[row*EDP + e] = __float2half(y * siluf(z));
            }
        }
        __syncthreads();
    }
}

// ---------------- logits mean/var (deterministic 2-pass) ----------------
__global__ void k_red1(){
    __shared__ float s1[32], s2[32];
    int base = blockIdx.x * 1024;
    float s = 0.f, q = 0.f;
    for (int i = threadIdx.x; i < 1024; i += 256){
        float v = g_logit[base + i];
        s += v; q += v*v;
    }
    for (int o = 16; o; o >>= 1){
        s += __shfl_down_sync(0xffffffffu, s, o);
        q += __shfl_down_sync(0xffffffffu, q, o);
    }
    if ((threadIdx.x & 31) == 0){ s1[threadIdx.x>>5] = s; s2[threadIdx.x>>5] = q; }
    __syncthreads();
    if (threadIdx.x < 32){
        float a = (threadIdx.x < 8) ? s1[threadIdx.x] : 0.f;
        float c = (threadIdx.x < 8) ? s2[threadIdx.x] : 0.f;
        for (int o = 4; o; o >>= 1){
            a += __shfl_down_sync(0xffffffffu, a, o);
            c += __shfl_down_sync(0xffffffffu, c, o);
        }
        if (threadIdx.x == 0){ g_part[blockIdx.x*2] = a; g_part[blockIdx.x*2+1] = c; }
    }
}

__global__ void k_red2(){
    __shared__ float s1[32], s2[32];
    float s = 0.f, q = 0.f;
    for (int i = threadIdx.x; i < 192; i += 256){ s += g_part[i*2]; q += g_part[i*2+1]; }
    for (int o = 16; o; o >>= 1){
        s += __shfl_down_sync(0xffffffffu, s, o);
        q += __shfl_down_sync(0xffffffffu, q, o);
    }
    if ((threadIdx.x & 31) == 0){ s1[threadIdx.x>>5] = s; s2[threadIdx.x>>5] = q; }
    __syncthreads();
    if (threadIdx.x == 0){
        float a = 0.f, c = 0.f;
        for (int i = 0; i < 8; i++){ a += s1[i]; c += s2[i]; }
        const float T = (float)(NR*VOC);
        float mean = a / T;
        float var  = c / T - mean*mean;
        g_stats[0] = mean;
        g_stats[1] = rsqrtf(var + EPSF);
    }
}

__global__ void k_nrm(){
    int i = blockIdx.x*blockDim.x + threadIdx.x;
    if (i < NR*VOC) h_nrm[i] = __float2half((g_logit[i] - g_stats[0]) * g_stats[1]);
}

__global__ void k_wesum(const float* __restrict__ emb_w){
    int o = threadIdx.x;
    float s = 0.f;
    for (int v = 0; v < VOC; v++) s += emb_w[o*VOC + v];
    g_wesum[o] = s;
}

// ---------------- final expand over f ----------------
__global__ void k_final(const float* __restrict__ bnw, const float* __restrict__ bnb,
                        const float* __restrict__ embb, float* __restrict__ out){
    int i = blockIdx.x*blockDim.x + threadIdx.x;
    const int total = BSZ*5*SEQ*OE;
    if (i >= total) return;
    int o = i & 255;
    int s = (i >> 8) % SEQ;
    int f = (i / (OE*SEQ)) % 5;
    int b = i / (OE*SEQ*5);
    int n = b*SEQ + s;
    out[i] = bnw[f]*g_t[(size_t)n*OE + o] + bnb[f]*g_wesum[o] + embb[o];
}

// ---------------- launch ----------------
extern "C" void kernel_launch(void* const* d_in, const int* in_sizes, int n_in,
                              void* d_out, int out_size)
{
    const float* x        = (const float*)d_in[0];
    const float* in_w     = (const float*)d_in[1];
    const float* conv_w   = (const float*)d_in[2];
    const float* conv_b   = (const float*)d_in[3];
    const float* xp_w     = (const float*)d_in[4];
    const float* dt_w     = (const float*)d_in[5];
    const float* dt_b     = (const float*)d_in[6];
    const float* A_log    = (const float*)d_in[7];
    const float* D_param  = (const float*)d_in[8];
    const float* out_w    = (const float*)d_in[9];
    const float* norm_w   = (const float*)d_in[10];
    const float* normf_w  = (const float*)d_in[11];
    const float* lm_w     = (const float*)d_in[12];
    const float* bn_w     = (const float*)d_in[13];
    const float* bn_b     = (const float*)d_in[14];
    const float* emb_w    = (const float*)d_in[15];
    const float* emb_b    = (const float*)d_in[16];
    float* out = (float*)d_out;

    cudaFuncSetAttribute(k_hmma256, cudaFuncAttributeMaxDynamicSharedMemorySize, (int)SMEM256);
    cudaFuncSetAttribute(k_hmma<4>, cudaFuncAttributeMaxDynamicSharedMemorySize, (int)SMEMH4);
    cudaFuncSetAttribute(k_hmma<2>, cudaFuncAttributeMaxDynamicSharedMemorySize, (int)SMEMH2);

    float *pxz, *pxc, *pdbc, *pdelta, *ph, *plog, *pt, *pnegA;
    __half *qxn, *qinw, *qxct, *qxpw, *qdbc, *qdtw, *qys, *qoutw, *qlmw, *qnrm, *qembw;
    cudaGetSymbolAddress((void**)&ph,     g_h);
    cudaGetSymbolAddress((void**)&pxz,    g_xz);
    cudaGetSymbolAddress((void**)&pxc,    g_xc);
    cudaGetSymbolAddress((void**)&pdbc,   g_dbc);
    cudaGetSymbolAddress((void**)&pdelta, g_delta);
    cudaGetSymbolAddress((void**)&plog,   g_logit);
    cudaGetSymbolAddress((void**)&pt,     g_t);
    cudaGetSymbolAddress((void**)&pnegA,  g_negA);
    cudaGetSymbolAddress((void**)&qxn,    h_xn);
    cudaGetSymbolAddress((void**)&qinw,   h_inw);
    cudaGetSymbolAddress((void**)&qxct,   h_xct);
    cudaGetSymbolAddress((void**)&qxpw,   h_xpw);
    cudaGetSymbolAddress((void**)&qdbc,   h_dbc);
    cudaGetSymbolAddress((void**)&qdtw,   h_dtw);
    cudaGetSymbolAddress((void**)&qys,    h_ys);
    cudaGetSymbolAddress((void**)&qoutw,  h_outw);
    cudaGetSymbolAddress((void**)&qlmw,   h_lmw);
    cudaGetSymbolAddress((void**)&qnrm,   h_nrm);
    cudaGetSymbolAddress((void**)&qembw,  h_embw);

    // launches 0..3: profiled launch (index 3) = big in_proj GEMM (k_hmma256)
    k_transpose_in<<<(NR*DM + 255)/256, 256>>>(x);                          // 0
    k_cvt2<<<2*2*ED, 256>>>(in_w, qinw, DM, DMP);                           // 1
    k_rmsnorm<<<NR, 256>>>(norm_w);                                         // 2
    k_hmma256<<<dim3(49, 6), 256, SMEM256>>>(                               // 3 <- profiled
        qxn, DMP, qinw, DMP, pxz, 2*ED, NR, 2*ED, DMP, 0);

    // remaining weight conversions
    k_cvt2<<<2*DM, 256>>>(out_w, qoutw, ED, EDP);
    k_cvt2<<<2*DBCN, 256>>>(xp_w, qxpw, ED, EDP);
    k_cvtw<<<(2*ED*DTR + 255)/256, 256>>>(dt_w, qdtw, DTR, DTKP, 2*ED*DTR);
    k_negA<<<(2*ED*DS + 255)/256, 256>>>(A_log);

    for (int l = 0; l < 2; l++){
        if (l == 1){
            k_rmsnorm<<<NR, 256>>>(norm_w + DM);
            k_hmma256<<<dim3(49, 6), 256, SMEM256>>>(
                qxn, DMP, qinw + (size_t)2*ED*DMP, DMP, pxz, 2*ED, NR, 2*ED, DMP, 0);
        }
        k_conv_silu<<<dim3((ED+255)/256, BSZ), 256>>>(conv_w + (size_t)l*ED*4, conv_b + l*ED);
        // dbc = xct @ xp_w^T  (1536 x 129, K=3136)
        k_hmma<2><<<dim3(2, 24), 256, SMEMH2>>>(
            qxct, EDP, qxpw + (size_t)l*DBCN*EDP, EDP, pdbc, DBCP, NR, DBCN, EDP, 3, nullptr, qdbc, DTKP);
        // delta = softplus(dt @ dtw^T + dt_b)  (1536 x 3100, K=128)
        k_hmma<4><<<dim3(25, 12), 256, SMEMH4>>>(
            qdbc, DTKP, qdtw + (size_t)l*ED*DTKP, DTKP, pdelta, ED, NR, ED, DTKP, 2, dt_b + l*ED, nullptr, 0);
        // scan -> h_ys  (grid: 13 e-slices x 32 batch-groups of 16)
        k_scan<<<dim3((ED+255)/256, BSZ/SCAN_BB), 256>>>(pnegA + (size_t)l*ED*DS, D_param + l*ED);
        // h += ys @ out_w^T  (1536 x 1550, K=3136)
        k_hmma256<<<dim3(13, 6), 256, SMEM256>>>(
            qys, EDP, qoutw + (size_t)l*DM*EDP, EDP, ph, DM, NR, DM, EDP, 1);
    }

    k_rmsnorm<<<NR, 256>>>(normf_w);
    k_cvt2<<<VOC, 256>>>(lm_w, qlmw, DM, DMP);
    // logits = xn @ lm_w^T  (1536 x 128, K=1600)
    k_hmma<2><<<dim3(1, 24), 256, SMEMH2>>>(
        qxn, DMP, qlmw, DMP, plog, VOC, NR, VOC, DMP, 0, nullptr, nullptr, 0);
    k_red1<<<192, 256>>>();
    k_red2<<<1, 256>>>();
    k_nrm<<<(NR*VOC + 255)/256, 256>>>();
    k_cvt2<<<OE, 256>>>(emb_w, qembw, VOC, VOC);
    // t = nrm @ emb_w^T  (1536 x 256, K=128)
    k_hmma<2><<<dim3(2, 24), 256, SMEMH2>>>(
        qnrm, VOC, qembw, VOC, pt, OE, NR, OE, VOC, 0, nullptr, nullptr, 0);
    k_wesum<<<1, 256>>>(emb_w);
    k_final<<<(BSZ*5*SEQ*OE + 255)/256, 256>>>(bn_w, bn_b, emb_b, out);
}

// round 12
// speedup vs baseline: 1.1867x; 1.1867x over previous
#include <cuda_runtime.h>
#include <cuda_fp16.h>
#include <math.h>
#include <stdint.h>

// ---------------- problem constants ----------------
#define BSZ   512
#define SEQ   3
#define DM    1550
#define DMP   1600          // DM padded to x64
#define DS    16
#define ED    3100
#define EDP   3136          // ED padded to x64
#define DTR   97
#define DTKP  128           // dt GEMM K padded
#define DBCN  129
#define DBCP  132           // fp32 dbc ldc
#define VOC   128
#define NR    (BSZ*SEQ)
#define OE    256
#define EPSF  1e-5f

#define SROW  72            // smem row stride in halves (BK=64 + 8 pad)
#define NSTG  3

#define SPL_DBC 7           // dbc split-K (7 x 448 halves = 3136)
#define SPL_LM  5           // lm  split-K (5 x 320 = 1600)
#define SPL_OUT 2           // out split-K (1600 + 1536)

// ---------------- fp32 scratch ----------------
__device__ __align__(256) float g_h    [NR*DM];
__device__ __align__(256) float g_xz   [NR*2*ED];
__device__ __align__(256) float g_xc   [NR*ED];
__device__ __align__(256) float g_dbc  [NR*DBCP];
__device__ __align__(256) float g_delta[NR*ED];
__device__ __align__(256) float g_negA [2*ED*DS];
__device__ __align__(256) float g_logit[NR*VOC];
__device__ __align__(256) float g_t    [NR*OE];
__device__ __align__(256) float g_split[2*NR*DM];   // split-K partials (19MB, covers all uses)
__device__ float g_part [384];
__device__ float g_stats[2];
__device__ float g_wesum[OE];

// ---------------- fp16 GEMM operand scratch (zero-init pads) ----------------
__device__ __align__(256) __half h_xn  [NR*DMP];
__device__ __align__(256) __half h_inw [2*2*ED*DMP];
__device__ __align__(256) __half h_xct [NR*EDP];
__device__ __align__(256) __half h_xpw [2*DBCN*EDP];
__device__ __align__(256) __half h_dbc [NR*DTKP];
__device__ __align__(256) __half h_dtw [2*ED*DTKP];
__device__ __align__(256) __half h_ys  [NR*EDP];
__device__ __align__(256) __half h_outw[2*DM*EDP];
__device__ __align__(256) __half h_lmw [VOC*DMP];
__device__ __align__(256) __half h_nrm [NR*VOC];
__device__ __align__(256) __half h_embw[OE*VOC];

__device__ __forceinline__ float siluf(float v){ return v / (1.f + expf(-v)); }

__device__ __forceinline__ void mma_f16(float c[4],
    uint32_t a0, uint32_t a1, uint32_t a2, uint32_t a3,
    uint32_t b0, uint32_t b1)
{
    asm volatile(
        "mma.sync.aligned.m16n8k16.row.col.f32.f16.f16.f32 "
        "{%0,%1,%2,%3}, {%4,%5,%6,%7}, {%8,%9}, {%0,%1,%2,%3};"
        : "+f"(c[0]), "+f"(c[1]), "+f"(c[2]), "+f"(c[3])
        : "r"(a0), "r"(a1), "r"(a2), "r"(a3), "r"(b0), "r"(b1));
}

__device__ __forceinline__ void cpa16(uint32_t sdst, const __half* gsrc, int nbytes){
    asm volatile("cp.async.cg.shared.global [%0], [%1], 16, %2;"
                 :: "r"(sdst), "l"(gsrc), "r"(nbytes));
}

__device__ __forceinline__ void ldsm4(uint32_t r[4], uint32_t addr){
    asm volatile("ldmatrix.sync.aligned.m8n8.x4.shared.b16 {%0,%1,%2,%3}, [%4];"
        : "=r"(r[0]), "=r"(r[1]), "=r"(r[2]), "=r"(r[3]) : "r"(addr));
}

// ================= k_h512: 16-warp (4x4) GEMM, tile 256x128, mode 0 only =================
// C[M,N] = A[M,K] * B[N,K]^T. Requirements: M%256==0, K%64==0, K>=128.
__global__ void __launch_bounds__(512, 1) k_h512(
    const __half* __restrict__ A, int lda,
    const __half* __restrict__ B, int ldb,
    float* __restrict__ C, int ldc,
    int M, int N, int K)
{
    extern __shared__ __half smh[];
    __half* As = smh;                       // [NSTG][256][SROW]
    __half* Bs = smh + NSTG*256*SROW;       // [NSTG][128][SROW]

    const int tid  = threadIdx.x;
    const int wid  = tid >> 5, lane = tid & 31;
    const int g    = lane >> 2, tg = lane & 3;
    const int wm   = (wid >> 2) * 64;       // 4 warp-rows
    const int wn   = (wid & 3) * 32;        // 4 warp-cols
    const int bm   = blockIdx.y * 256;
    const int bn   = blockIdx.x * 128;
    const int lrow = tid >> 3;              // 0..63
    const int lcol = (tid & 7) * 8;

    const uint32_t sA = (uint32_t)__cvta_generic_to_shared(As);
    const uint32_t sB = (uint32_t)__cvta_generic_to_shared(Bs);

    uint32_t aaddr[4], baddr[2];
    {
        int arow = wm + (lane & 15);
        int acol = ((lane >> 4) & 1) * 8;
        #pragma unroll
        for (int mt = 0; mt < 4; mt++)
            aaddr[mt] = sA + (uint32_t)(((arow + mt*16)*SROW + acol)*2);
        #pragma unroll
        for (int ntp = 0; ntp < 2; ntp++){
            int brow = wn + ntp*16 + (lane & 7) + ((lane >> 4) & 1)*8;
            int bcol = ((lane >> 3) & 1) * 8;
            baddr[ntp] = sB + (uint32_t)((brow*SROW + bcol)*2);
        }
    }

    float acc[4][4][4];
    #pragma unroll
    for (int mt = 0; mt < 4; mt++)
        #pragma unroll
        for (int nt = 0; nt < 4; nt++)
            #pragma unroll
            for (int i = 0; i < 4; i++) acc[mt][nt][i] = 0.f;

    const int nch = K >> 6;

    auto issue = [&](int c){
        const int gk = c*64 + lcol;
        const int s  = c % NSTG;
        uint32_t da = sA + (uint32_t)((s*256*SROW + lrow*SROW + lcol)*2);
        #pragma unroll
        for (int p = 0; p < 4; p++)
            cpa16(da + (uint32_t)(p*64*SROW*2),
                  A + (size_t)(bm + lrow + p*64)*lda + gk, 16);
        uint32_t db = sB + (uint32_t)((s*128*SROW + lrow*SROW + lcol)*2);
        #pragma unroll
        for (int p = 0; p < 2; p++){
            int gn = bn + lrow + p*64;
            cpa16(db + (uint32_t)(p*64*SROW*2),
                  B + (size_t)(gn < N ? gn : 0)*ldb + gk, (gn < N) ? 16 : 0);
        }
        asm volatile("cp.async.commit_group;");
    };

    issue(0);
    issue(1);
    for (int c = 0; c < nch; c++){
        if (c + 1 < nch) asm volatile("cp.async.wait_group 1;");
        else             asm volatile("cp.async.wait_group 0;");
        __syncthreads();
        if (c + 2 < nch) issue(c + 2);

        const uint32_t offA = (uint32_t)((c % NSTG)*256*SROW*2);
        const uint32_t offB = (uint32_t)((c % NSTG)*128*SROW*2);
        #pragma unroll
        for (int kst = 0; kst < 4; kst++){
            uint32_t af[4][4], bfr[2][4];
            #pragma unroll
            for (int mt = 0; mt < 4; mt++)
                ldsm4(af[mt], aaddr[mt] + offA + kst*32);
            #pragma unroll
            for (int ntp = 0; ntp < 2; ntp++)
                ldsm4(bfr[ntp], baddr[ntp] + offB + kst*32);
            #pragma unroll
            for (int mt = 0; mt < 4; mt++)
                #pragma unroll
                for (int nt = 0; nt < 4; nt++)
                    mma_f16(acc[mt][nt],
                            af[mt][0], af[mt][1], af[mt][2], af[mt][3],
                            bfr[nt >> 1][(nt & 1)*2], bfr[nt >> 1][(nt & 1)*2 + 1]);
        }
    }

    #pragma unroll
    for (int mt = 0; mt < 4; mt++){
        int r0 = bm + wm + mt*16 + g;
        #pragma unroll
        for (int nt = 0; nt < 4; nt++){
            int cl = bn + wn + nt*8 + 2*tg;
            #pragma unroll
            for (int i = 0; i < 4; i++){
                int rr = r0 + (i >> 1)*8;
                int cc = cl + (i & 1);
                if (cc < N) C[(size_t)rr*ldc + cc] = acc[mt][nt][i];
            }
        }
    }
}
#define SMEM512 (NSTG*(256+128)*SROW*sizeof(__half))   // 165888

// ---------------- k_hmma: 8-warp 2x4 kernel, optional split-K ----------------
// gk range [z*KS, min(K, (z+1)*KS)). mode 0: C = acc ; 1: C += acc ;
// 2: softplus(acc+bias) ; 4: partial write to C + z*M*ldc.
template<int MT>
__global__ void __launch_bounds__(256, 2) k_hmma(
    const __half* __restrict__ A, int lda,
    const __half* __restrict__ B, int ldb,
    float* __restrict__ C, int ldc,
    int M, int N, int K, int KS,
    int mode, const float* __restrict__ bias)
{
    constexpr int BM = MT*32;
    extern __shared__ __half smh[];
    __half* As = smh;
    __half* Bs = smh + NSTG*BM*SROW;

    const int tid  = threadIdx.x;
    const int wid  = tid >> 5, lane = tid & 31;
    const int g    = lane >> 2, tg = lane & 3;
    const int wm   = (wid >> 2) * (MT*16);
    const int wn   = (wid & 3) * 32;
    const int bm   = blockIdx.y * BM;
    const int bn   = blockIdx.x * 128;
    const int lrow = tid >> 3;
    const int lcol = (tid & 7) * 8;
    const int k0   = blockIdx.z * KS;
    const int nch  = (((K - k0) < KS ? (K - k0) : KS)) >> 6;
    if (mode == 4) C += (size_t)blockIdx.z * (size_t)M * ldc;

    const uint32_t sA = (uint32_t)__cvta_generic_to_shared(As);
    const uint32_t sB = (uint32_t)__cvta_generic_to_shared(Bs);

    uint32_t aaddr[MT], baddr[2];
    {
        int arow = wm + (lane & 15);
        int acol = ((lane >> 4) & 1) * 8;
        #pragma unroll
        for (int mt = 0; mt < MT; mt++)
            aaddr[mt] = sA + (uint32_t)(((arow + mt*16)*SROW + acol)*2);
        #pragma unroll
        for (int ntp = 0; ntp < 2; ntp++){
            int brow = wn + ntp*16 + (lane & 7) + ((lane >> 4) & 1)*8;
            int bcol = ((lane >> 3) & 1) * 8;
            baddr[ntp] = sB + (uint32_t)((brow*SROW + bcol)*2);
        }
    }

    float acc[MT][4][4];
    #pragma unroll
    for (int mt = 0; mt < MT; mt++)
        #pragma unroll
        for (int nt = 0; nt < 4; nt++)
            #pragma unroll
            for (int i = 0; i < 4; i++) acc[mt][nt][i] = 0.f;

    auto issue = [&](int c){
        const int gk = k0 + c*64 + lcol;
        const int s  = c % NSTG;
        uint32_t da = sA + (uint32_t)((s*BM*SROW + lrow*SROW + lcol)*2);
        #pragma unroll
        for (int p = 0; p < BM/32; p++)
            cpa16(da + (uint32_t)(p*32*SROW*2),
                  A + (size_t)(bm + lrow + p*32)*lda + gk, 16);
        uint32_t db = sB + (uint32_t)((s*128*SROW + lrow*SROW + lcol)*2);
        #pragma unroll
        for (int p = 0; p < 4; p++){
            int gn = bn + lrow + p*32;
            cpa16(db + (uint32_t)(p*32*SROW*2),
                  B + (size_t)(gn < N ? gn : 0)*ldb + gk, (gn < N) ? 16 : 0);
        }
        asm volatile("cp.async.commit_group;");
    };

    issue(0);
    issue(1);
    for (int c = 0; c < nch; c++){
        if (c + 1 < nch) asm volatile("cp.async.wait_group 1;");
        else             asm volatile("cp.async.wait_group 0;");
        __syncthreads();
        if (c + 2 < nch) issue(c + 2);

        const uint32_t offA = (uint32_t)((c % NSTG)*BM*SROW*2);
        const uint32_t offB = (uint32_t)((c % NSTG)*128*SROW*2);
        #pragma unroll
        for (int kst = 0; kst < 4; kst++){
            uint32_t af[MT][4], bfr[2][4];
            #pragma unroll
            for (int mt = 0; mt < MT; mt++)
                ldsm4(af[mt], aaddr[mt] + offA + kst*32);
            #pragma unroll
            for (int ntp = 0; ntp < 2; ntp++)
                ldsm4(bfr[ntp], baddr[ntp] + offB + kst*32);
            #pragma unroll
            for (int mt = 0; mt < MT; mt++)
                #pragma unroll
                for (int nt = 0; nt < 4; nt++)
                    mma_f16(acc[mt][nt],
                            af[mt][0], af[mt][1], af[mt][2], af[mt][3],
                            bfr[nt >> 1][(nt & 1)*2], bfr[nt >> 1][(nt & 1)*2 + 1]);
        }
    }

    #pragma unroll
    for (int mt = 0; mt < MT; mt++){
        int r0 = bm + wm + mt*16 + g;
        #pragma unroll
        for (int nt = 0; nt < 4; nt++){
            int cl = bn + wn + nt*8 + 2*tg;
            #pragma unroll
            for (int i = 0; i < 4; i++){
                int rr = r0 + (i >> 1)*8;
                int cc = cl + (i & 1);
                if (cc >= N) continue;
                float v = acc[mt][nt][i];
                size_t idx = (size_t)rr*ldc + cc;
                if (mode == 1){
                    v += C[idx];
                } else if (mode == 2){
                    float xv = v + bias[cc];
                    v = fmaxf(xv, 0.f) + log1pf(expf(-fabsf(xv)));
                }
                C[idx] = v;
            }
        }
    }
}

#define SMEMH4 (NSTG*(128+128)*SROW*sizeof(__half))   // 110592
#define SMEMH2 (NSTG*(64 +128)*SROW*sizeof(__half))   // 82944

// ---------------- split-K reductions (deterministic fixed order) ----------------
__global__ void k_reddbc(){
    int i = blockIdx.x*blockDim.x + threadIdx.x;
    if (i >= NR*DBCN) return;
    int r = i / DBCN, c = i % DBCN;
    float s = 0.f;
    #pragma unroll
    for (int z = 0; z < SPL_DBC; z++)
        s += g_split[(size_t)z*NR*DBCP + (size_t)r*DBCP + c];
    g_dbc[(size_t)r*DBCP + c] = s;
    if (c < DTR) h_dbc[(size_t)r*DTKP + c] = __float2half(s);
}

__global__ void k_redlm(){
    int i = blockIdx.x*blockDim.x + threadIdx.x;
    if (i >= NR*VOC) return;
    float s = 0.f;
    #pragma unroll
    for (int z = 0; z < SPL_LM; z++)
        s += g_split[(size_t)z*NR*VOC + i];
    g_logit[i] = s;
}

__global__ void k_redout(){
    int i = blockIdx.x*blockDim.x + threadIdx.x;
    if (i >= NR*DM) return;
    g_h[i] += g_split[i] + g_split[(size_t)NR*DM + i];
}

// ---------------- vectorized fp32 -> padded fp16 ----------------
__global__ void k_cvt2(const float* __restrict__ src, __half* __restrict__ dst,
                       int K, int KP){
    int r = blockIdx.x;
    const float2* s = (const float2*)(src + (size_t)r*K);
    __half* d = dst + (size_t)r*KP;
    const int n2 = K >> 1;
    for (int i = threadIdx.x; i < n2; i += blockDim.x){
        float2 v = s[i];
        *(__half2*)(d + 2*i) = __floats2half2_rn(v.x, v.y);
    }
}

__global__ void k_cvtw(const float* __restrict__ src, __half* __restrict__ dst,
                       int K, int KP, int n){
    int i = blockIdx.x*blockDim.x + threadIdx.x;
    if (i < n) dst[(size_t)(i/K)*KP + (i%K)] = __float2half(src[i]);
}

// ---------------- input transpose ----------------
__global__ void k_transpose_in(const float* __restrict__ x){
    int i = blockIdx.x*blockDim.x + threadIdx.x;
    if (i >= NR*DM) return;
    int n = i / DM, d = i % DM;
    int c = d / 25, r = d % 25, f = r / 5, e = r % 5;
    g_h[i] = x[((n*5 + f)*62 + c)*5 + e];
}

// ---------------- rmsnorm: g_h -> h_xn (fp16, padded) ----------------
__global__ void k_rmsnorm(const float* __restrict__ w){
    __shared__ float sh[33];
    int n = blockIdx.x;
    const float* row = g_h + (size_t)n*DM;
    float ss = 0.f;
    for (int d = threadIdx.x; d < DM; d += blockDim.x){ float v = row[d]; ss += v*v; }
    for (int o = 16; o; o >>= 1) ss += __shfl_down_sync(0xffffffffu, ss, o);
    if ((threadIdx.x & 31) == 0) sh[threadIdx.x >> 5] = ss;
    __syncthreads();
    if (threadIdx.x < 32){
        float v = (threadIdx.x < (int)(blockDim.x >> 5)) ? sh[threadIdx.x] : 0.f;
        for (int o = 16; o; o >>= 1) v += __shfl_down_sync(0xffffffffu, v, o);
        if (threadIdx.x == 0) sh[32] = rsqrtf(v / (float)DM + EPSF);
    }
    __syncthreads();
    float sc = sh[32];
    for (int d = threadIdx.x; d < DM; d += blockDim.x)
        h_xn[(size_t)n*DMP + d] = __float2half(row[d] * sc * w[d]);
}

// ---------------- depthwise causal conv + silu ----------------
__global__ void k_conv_silu(const float* __restrict__ cw, const float* __restrict__ cb){
    int e = blockIdx.x*blockDim.x + threadIdx.x;
    int b = blockIdx.y;
    if (e >= ED) return;
    size_t r0 = (size_t)(b*SEQ + 0)*(2*ED);
    size_t r1 = (size_t)(b*SEQ + 1)*(2*ED);
    size_t r2 = (size_t)(b*SEQ + 2)*(2*ED);
    float x0 = g_xz[r0 + e], x1 = g_xz[r1 + e], x2 = g_xz[r2 + e];
    float w1 = cw[e*4+1], w2 = cw[e*4+2], w3 = cw[e*4+3];
    float bb = cb[e];
    float y0 = siluf(bb + w3*x0);
    float y1 = siluf(bb + w2*x0 + w3*x1);
    float y2 = siluf(bb + w1*x0 + w2*x1 + w3*x2);
    g_xc[(size_t)(b*SEQ + 0)*ED + e] = y0;  h_xct[(size_t)(b*SEQ + 0)*EDP + e] = __float2half(y0);
    g_xc[(size_t)(b*SEQ + 1)*ED + e] = y1;  h_xct[(size_t)(b*SEQ + 1)*EDP + e] = __float2half(y1);
    g_xc[(size_t)(b*SEQ + 2)*ED + e] = y2;  h_xct[(size_t)(b*SEQ + 2)*EDP + e] = __float2half(y2);
}

// ---------------- negA (both layers) ----------------
__global__ void k_negA(const float* __restrict__ Alog){
    int i = blockIdx.x*blockDim.x + threadIdx.x;
    if (i < 2*ED*DS) g_negA[i] = -expf(Alog[i]);
}

// ---------------- fused SSM scan: block = e-slice, loops 16 batches ----------------
#define SCAN_BB 16
__global__ void k_scan(const float* __restrict__ nAbase, const float* __restrict__ Dp){
    __shared__ float sB[SEQ][DS], sC[SEQ][DS];
    int e = blockIdx.x*blockDim.x + threadIdx.x;
    int t = threadIdx.x;
    bool act = (e < ED);

    float nA[DS], dpe = 0.f;
    if (act){
        #pragma unroll
        for (int n = 0; n < DS; n++) nA[n] = nAbase[e*DS + n];
        dpe = Dp[e];
    }

    for (int bb = 0; bb < SCAN_BB; bb++){
        int b = blockIdx.y*SCAN_BB + bb;
        if (t < SEQ*DS){
            int s = t / DS, n = t % DS;
            size_t base = (size_t)(b*SEQ + s)*DBCP + DTR;
            sB[s][n] = g_dbc[base + n];
            sC[s][n] = g_dbc[base + DS + n];
        }
        __syncthreads();
        if (act){
            float hst[DS];
            #pragma unroll
            for (int n = 0; n < DS; n++) hst[n] = 0.f;
            #pragma unroll
            for (int s = 0; s < SEQ; s++){
                size_t row = (size_t)(b*SEQ + s);
                float d   = g_delta[row*ED + e];
                float xcv = g_xc[row*ED + e];
                float dx  = d * xcv;
                float y = 0.f;
                #pragma unroll
                for (int n = 0; n < DS; n++){
                    float dA = __expf(d * nA[n]);
                    hst[n] = dA*hst[n] + dx*sB[s][n];
                    y = fmaf(hst[n], sC[s][n], y);
                }
                y += dpe * xcv;
                float z = g_xz[row*(2*ED) + ED + e];
                h_ys[row*EDP + e] = __float2half(y * siluf(z));
            }
        }
        __syncthreads();
    }
}

// ---------------- logits mean/var (deterministic 2-pass) ----------------
__global__ void k_red1(){
    __shared__ float s1[32], s2[32];
    int base = blockIdx.x * 1024;
    float s = 0.f, q = 0.f;
    for (int i = threadIdx.x; i < 1024; i += 256){
        float v = g_logit[base + i];
        s += v; q += v*v;
    }
    for (int o = 16; o; o >>= 1){
        s += __shfl_down_sync(0xffffffffu, s, o);
        q += __shfl_down_sync(0xffffffffu, q, o);
    }
    if ((threadIdx.x & 31) == 0){ s1[threadIdx.x>>5] = s; s2[threadIdx.x>>5] = q; }
    __syncthreads();
    if (threadIdx.x < 32){
        float a = (threadIdx.x < 8) ? s1[threadIdx.x] : 0.f;
        float c = (threadIdx.x < 8) ? s2[threadIdx.x] : 0.f;
        for (int o = 4; o; o >>= 1){
            a += __shfl_down_sync(0xffffffffu, a, o);
            c += __shfl_down_sync(0xffffffffu, c, o);
        }
        if (threadIdx.x == 0){ g_part[blockIdx.x*2] = a; g_part[blockIdx.x*2+1] = c; }
    }
}

__global__ void k_red2(){
    __shared__ float s1[32], s2[32];
    float s = 0.f, q = 0.f;
    for (int i = threadIdx.x; i < 192; i += 256){ s += g_part[i*2]; q += g_part[i*2+1]; }
    for (int o = 16; o; o >>= 1){
        s += __shfl_down_sync(0xffffffffu, s, o);
        q += __shfl_down_sync(0xffffffffu, q, o);
    }
    if ((threadIdx.x & 31) == 0){ s1[threadIdx.x>>5] = s; s2[threadIdx.x>>5] = q; }
    __syncthreads();
    if (threadIdx.x == 0){
        float a = 0.f, c = 0.f;
        for (int i = 0; i < 8; i++){ a += s1[i]; c += s2[i]; }
        const float T = (float)(NR*VOC);
        float mean = a / T;
        float var  = c / T - mean*mean;
        g_stats[0] = mean;
        g_stats[1] = rsqrtf(var + EPSF);
    }
}

__global__ void k_nrm(){
    int i = blockIdx.x*blockDim.x + threadIdx.x;
    if (i < NR*VOC) h_nrm[i] = __float2half((g_logit[i] - g_stats[0]) * g_stats[1]);
}

__global__ void k_wesum(const float* __restrict__ emb_w){
    int o = threadIdx.x;
    float s = 0.f;
    for (int v = 0; v < VOC; v++) s += emb_w[o*VOC + v];
    g_wesum[o] = s;
}

// ---------------- final expand over f ----------------
__global__ void k_final(const float* __restrict__ bnw, const float* __restrict__ bnb,
                        const float* __restrict__ embb, float* __restrict__ out){
    int i = blockIdx.x*blockDim.x + threadIdx.x;
    const int total = BSZ*5*SEQ*OE;
    if (i >= total) return;
    int o = i & 255;
    int s = (i >> 8) % SEQ;
    int f = (i / (OE*SEQ)) % 5;
    int b = i / (OE*SEQ*5);
    int n = b*SEQ + s;
    out[i] = bnw[f]*g_t[(size_t)n*OE + o] + bnb[f]*g_wesum[o] + embb[o];
}

// ---------------- launch ----------------
extern "C" void kernel_launch(void* const* d_in, const int* in_sizes, int n_in,
                              void* d_out, int out_size)
{
    const float* x        = (const float*)d_in[0];
    const float* in_w     = (const float*)d_in[1];
    const float* conv_w   = (const float*)d_in[2];
    const float* conv_b   = (const float*)d_in[3];
    const float* xp_w     = (const float*)d_in[4];
    const float* dt_w     = (const float*)d_in[5];
    const float* dt_b     = (const float*)d_in[6];
    const float* A_log    = (const float*)d_in[7];
    const float* D_param  = (const float*)d_in[8];
    const float* out_w    = (const float*)d_in[9];
    const float* norm_w   = (const float*)d_in[10];
    const float* normf_w  = (const float*)d_in[11];
    const float* lm_w     = (const float*)d_in[12];
    const float* bn_w     = (const float*)d_in[13];
    const float* bn_b     = (const float*)d_in[14];
    const float* emb_w    = (const float*)d_in[15];
    const float* emb_b    = (const float*)d_in[16];
    float* out = (float*)d_out;

    cudaFuncSetAttribute(k_h512,    cudaFuncAttributeMaxDynamicSharedMemorySize, (int)SMEM512);
    cudaFuncSetAttribute(k_hmma<4>, cudaFuncAttributeMaxDynamicSharedMemorySize, (int)SMEMH4);
    cudaFuncSetAttribute(k_hmma<2>, cudaFuncAttributeMaxDynamicSharedMemorySize, (int)SMEMH2);

    float *pxz, *pdelta, *ph, *plog, *pt, *pnegA, *psplit;
    __half *qxn, *qinw, *qxct, *qxpw, *qdbc, *qdtw, *qys, *qoutw, *qlmw, *qnrm, *qembw;
    cudaGetSymbolAddress((void**)&ph,     g_h);
    cudaGetSymbolAddress((void**)&pxz,    g_xz);
    cudaGetSymbolAddress((void**)&pdelta, g_delta);
    cudaGetSymbolAddress((void**)&plog,   g_logit);
    cudaGetSymbolAddress((void**)&pt,     g_t);
    cudaGetSymbolAddress((void**)&pnegA,  g_negA);
    cudaGetSymbolAddress((void**)&psplit, g_split);
    cudaGetSymbolAddress((void**)&qxn,    h_xn);
    cudaGetSymbolAddress((void**)&qinw,   h_inw);
    cudaGetSymbolAddress((void**)&qxct,   h_xct);
    cudaGetSymbolAddress((void**)&qxpw,   h_xpw);
    cudaGetSymbolAddress((void**)&qdbc,   h_dbc);
    cudaGetSymbolAddress((void**)&qdtw,   h_dtw);
    cudaGetSymbolAddress((void**)&qys,    h_ys);
    cudaGetSymbolAddress((void**)&qoutw,  h_outw);
    cudaGetSymbolAddress((void**)&qlmw,   h_lmw);
    cudaGetSymbolAddress((void**)&qnrm,   h_nrm);
    cudaGetSymbolAddress((void**)&qembw,  h_embw);

    // launches 0..3: profiled launch (index 3) = in_proj GEMM (k_h512)
    k_transpose_in<<<(NR*DM + 255)/256, 256>>>(x);                          // 0
    k_cvt2<<<2*2*ED, 256>>>(in_w, qinw, DM, DMP);                           // 1
    k_rmsnorm<<<NR, 256>>>(norm_w);                                         // 2
    k_h512<<<dim3(49, 6), 512, SMEM512>>>(                                  // 3 <- profiled
        qxn, DMP, qinw, DMP, pxz, 2*ED, NR, 2*ED, DMP);

    // remaining weight conversions
    k_cvt2<<<2*DM, 256>>>(out_w, qoutw, ED, EDP);
    k_cvt2<<<2*DBCN, 256>>>(xp_w, qxpw, ED, EDP);
    k_cvtw<<<(2*ED*DTR + 255)/256, 256>>>(dt_w, qdtw, DTR, DTKP, 2*ED*DTR);
    k_negA<<<(2*ED*DS + 255)/256, 256>>>(A_log);

    for (int l = 0; l < 2; l++){
        if (l == 1){
            k_rmsnorm<<<NR, 256>>>(norm_w + DM);
            k_h512<<<dim3(49, 6), 512, SMEM512>>>(
                qxn, DMP, qinw + (size_t)2*ED*DMP, DMP, pxz, 2*ED, NR, 2*ED, DMP);
        }
        k_conv_silu<<<dim3((ED+255)/256, BSZ), 256>>>(conv_w + (size_t)l*ED*4, conv_b + l*ED);
        // dbc partials: xct @ xp_w^T  (1536 x 129, K=3136, split-K 7 x 448)
        k_hmma<2><<<dim3(2, 24, SPL_DBC), 256, SMEMH2>>>(
            qxct, EDP, qxpw + (size_t)l*DBCN*EDP, EDP, psplit, DBCP, NR, DBCN, EDP, 448, 4, nullptr);
        k_reddbc<<<(NR*DBCN + 255)/256, 256>>>();
        // delta = softplus(dt @ dtw^T + dt_b)  (1536 x 3100, K=128)
        k_hmma<4><<<dim3(25, 12), 256, SMEMH4>>>(
            qdbc, DTKP, qdtw + (size_t)l*ED*DTKP, DTKP, pdelta, ED, NR, ED, DTKP, DTKP, 2, dt_b + l*ED);
        // scan -> h_ys
        k_scan<<<dim3((ED+255)/256, BSZ/SCAN_BB), 256>>>(pnegA + (size_t)l*ED*DS, D_param + l*ED);
        // out_proj partials: ys @ out_w^T (1536 x 1550, K=3136, split-K 2 x 1600), then h +=
        k_hmma<4><<<dim3(13, 12, SPL_OUT), 256, SMEMH4>>>(
            qys, EDP, qoutw + (size_t)l*DM*EDP, EDP, psplit, DM, NR, DM, EDP, 1600, 4, nullptr);
        k_redout<<<(NR*DM + 255)/256, 256>>>();
    }

    k_rmsnorm<<<NR, 256>>>(normf_w);
    k_cvt2<<<VOC, 256>>>(lm_w, qlmw, DM, DMP);
    // logits partials: xn @ lm_w^T  (1536 x 128, K=1600, split-K 5 x 320)
    k_hmma<2><<<dim3(1, 24, SPL_LM), 256, SMEMH2>>>(
        qxn, DMP, qlmw, DMP, psplit, VOC, NR, VOC, DMP, 320, 4, nullptr);
    k_redlm<<<(NR*VOC + 255)/256, 256>>>();
    k_red1<<<192, 256>>>();
    k_red2<<<1, 256>>>();
    k_nrm<<<(NR*VOC + 255)/256, 256>>>();
    k_cvt2<<<OE, 256>>>(emb_w, qembw, VOC, VOC);
    // t = nrm @ emb_w^T  (1536 x 256, K=128)
    k_hmma<2><<<dim3(2, 24), 256, SMEMH2>>>(
        qnrm, VOC, qembw, VOC, pt, OE, NR, OE, VOC, VOC, 0, nullptr);
    k_wesum<<<1, 256>>>(emb_w);
    k_final<<<(BSZ*5*SEQ*OE + 255)/256, 256>>>(bn_w, bn_b, emb_b, out);
}

// round 13
// speedup vs baseline: 1.2350x; 1.0407x over previous
#include <cuda_runtime.h>
#include <cuda_fp16.h>
#include <math.h>
#include <stdint.h>

// ---------------- problem constants ----------------
#define BSZ   512
#define SEQ   3
#define DM    1550
#define DMP   1600          // DM padded to x64
#define DS    16
#define ED    3100
#define EDP   3136          // ED padded to x64
#define DTR   97
#define DTKP  128           // dt GEMM K padded
#define DBCN  129
#define DBCP  132           // fp32 dbc ldc
#define VOC   128
#define NR    (BSZ*SEQ)
#define OE    256
#define EPSF  1e-5f

#define SROW  72            // smem row stride in halves (BK=64 + 8 pad)
#define NSTG  3

#define SPL_DBC 7           // dbc split-K (7 x 448 = 3136)
#define SPL_LM  5           // lm  split-K (5 x 320 = 1600)
#define SPL_OUT 3           // out split-K (1088 + 1088 + 960 = 3136)

// ---------------- fp32 scratch ----------------
__device__ __align__(256) float g_h    [NR*DM];
__device__ __align__(256) float g_xz   [NR*2*ED];
__device__ __align__(256) float g_xc   [NR*ED];
__device__ __align__(256) float g_dbc  [NR*DBCP];
__device__ __align__(256) float g_delta[NR*ED];
__device__ __align__(256) float g_negA [2*ED*DS];
__device__ __align__(256) float g_logit[NR*VOC];
__device__ __align__(256) float g_t    [NR*OE];
__device__ __align__(256) float g_split[3*NR*DM];   // split-K partials (28.6MB, covers all uses)
__device__ float g_part [384];
__device__ float g_stats[2];
__device__ float g_wesum[OE];

// ---------------- fp16 GEMM operand scratch (zero-init pads) ----------------
__device__ __align__(256) __half h_xn  [NR*DMP];
__device__ __align__(256) __half h_inw [2*2*ED*DMP];
__device__ __align__(256) __half h_xct [NR*EDP];
__device__ __align__(256) __half h_xpw [2*DBCN*EDP];
__device__ __align__(256) __half h_dbc [NR*DTKP];
__device__ __align__(256) __half h_dtw [2*ED*DTKP];
__device__ __align__(256) __half h_ys  [NR*EDP];
__device__ __align__(256) __half h_outw[2*DM*EDP];
__device__ __align__(256) __half h_lmw [VOC*DMP];
__device__ __align__(256) __half h_nrm [NR*VOC];
__device__ __align__(256) __half h_embw[OE*VOC];

__device__ __forceinline__ float siluf(float v){ return v / (1.f + expf(-v)); }

__device__ __forceinline__ void mma_f16(float c[4],
    uint32_t a0, uint32_t a1, uint32_t a2, uint32_t a3,
    uint32_t b0, uint32_t b1)
{
    asm volatile(
        "mma.sync.aligned.m16n8k16.row.col.f32.f16.f16.f32 "
        "{%0,%1,%2,%3}, {%4,%5,%6,%7}, {%8,%9}, {%0,%1,%2,%3};"
        : "+f"(c[0]), "+f"(c[1]), "+f"(c[2]), "+f"(c[3])
        : "r"(a0), "r"(a1), "r"(a2), "r"(a3), "r"(b0), "r"(b1));
}

__device__ __forceinline__ void cpa16(uint32_t sdst, const __half* gsrc, int nbytes){
    asm volatile("cp.async.cg.shared.global [%0], [%1], 16, %2;"
                 :: "r"(sdst), "l"(gsrc), "r"(nbytes));
}

__device__ __forceinline__ void ldsm4(uint32_t r[4], uint32_t addr){
    asm volatile("ldmatrix.sync.aligned.m8n8.x4.shared.b16 {%0,%1,%2,%3}, [%4];"
        : "=r"(r[0]), "=r"(r[1]), "=r"(r[2]), "=r"(r[3]) : "r"(addr));
}

// ---------------- k_hmma: 8-warp 2x4 GEMM, optional split-K ----------------
// gk range [z*KS, min(K, (z+1)*KS)). mode 0: C = acc ; 1: C += acc ;
// 2: softplus(acc+bias) ; 4: partial write to C + z*M*ldc.
template<int MT>
__global__ void __launch_bounds__(256, 2) k_hmma(
    const __half* __restrict__ A, int lda,
    const __half* __restrict__ B, int ldb,
    float* __restrict__ C, int ldc,
    int M, int N, int K, int KS,
    int mode, const float* __restrict__ bias)
{
    constexpr int BM = MT*32;
    extern __shared__ __half smh[];
    __half* As = smh;
    __half* Bs = smh + NSTG*BM*SROW;

    const int tid  = threadIdx.x;
    const int wid  = tid >> 5, lane = tid & 31;
    const int g    = lane >> 2, tg = lane & 3;
    const int wm   = (wid >> 2) * (MT*16);
    const int wn   = (wid & 3) * 32;
    const int bm   = blockIdx.y * BM;
    const int bn   = blockIdx.x * 128;
    const int lrow = tid >> 3;
    const int lcol = (tid & 7) * 8;
    const int k0   = blockIdx.z * KS;
    const int nch  = (((K - k0) < KS ? (K - k0) : KS)) >> 6;
    if (mode == 4) C += (size_t)blockIdx.z * (size_t)M * ldc;

    const uint32_t sA = (uint32_t)__cvta_generic_to_shared(As);
    const uint32_t sB = (uint32_t)__cvta_generic_to_shared(Bs);

    uint32_t aaddr[MT], baddr[2];
    {
        int arow = wm + (lane & 15);
        int acol = ((lane >> 4) & 1) * 8;
        #pragma unroll
        for (int mt = 0; mt < MT; mt++)
            aaddr[mt] = sA + (uint32_t)(((arow + mt*16)*SROW + acol)*2);
        #pragma unroll
        for (int ntp = 0; ntp < 2; ntp++){
            int brow = wn + ntp*16 + (lane & 7) + ((lane >> 4) & 1)*8;
            int bcol = ((lane >> 3) & 1) * 8;
            baddr[ntp] = sB + (uint32_t)((brow*SROW + bcol)*2);
        }
    }

    float acc[MT][4][4];
    #pragma unroll
    for (int mt = 0; mt < MT; mt++)
        #pragma unroll
        for (int nt = 0; nt < 4; nt++)
            #pragma unroll
            for (int i = 0; i < 4; i++) acc[mt][nt][i] = 0.f;

    auto issue = [&](int c){
        const int gk = k0 + c*64 + lcol;
        const int s  = c % NSTG;
        uint32_t da = sA + (uint32_t)((s*BM*SROW + lrow*SROW + lcol)*2);
        #pragma unroll
        for (int p = 0; p < BM/32; p++)
            cpa16(da + (uint32_t)(p*32*SROW*2),
                  A + (size_t)(bm + lrow + p*32)*lda + gk, 16);
        uint32_t db = sB + (uint32_t)((s*128*SROW + lrow*SROW + lcol)*2);
        #pragma unroll
        for (int p = 0; p < 4; p++){
            int gn = bn + lrow + p*32;
            cpa16(db + (uint32_t)(p*32*SROW*2),
                  B + (size_t)(gn < N ? gn : 0)*ldb + gk, (gn < N) ? 16 : 0);
        }
        asm volatile("cp.async.commit_group;");
    };

    issue(0);
    issue(1);
    for (int c = 0; c < nch; c++){
        if (c + 1 < nch) asm volatile("cp.async.wait_group 1;");
        else             asm volatile("cp.async.wait_group 0;");
        __syncthreads();
        if (c + 2 < nch) issue(c + 2);

        const uint32_t offA = (uint32_t)((c % NSTG)*BM*SROW*2);
        const uint32_t offB = (uint32_t)((c % NSTG)*128*SROW*2);
        #pragma unroll
        for (int kst = 0; kst < 4; kst++){
            uint32_t af[MT][4], bfr[2][4];
            #pragma unroll
            for (int mt = 0; mt < MT; mt++)
                ldsm4(af[mt], aaddr[mt] + offA + kst*32);
            #pragma unroll
            for (int ntp = 0; ntp < 2; ntp++)
                ldsm4(bfr[ntp], baddr[ntp] + offB + kst*32);
            #pragma unroll
            for (int mt = 0; mt < MT; mt++)
                #pragma unroll
                for (int nt = 0; nt < 4; nt++)
                    mma_f16(acc[mt][nt],
                            af[mt][0], af[mt][1], af[mt][2], af[mt][3],
                            bfr[nt >> 1][(nt & 1)*2], bfr[nt >> 1][(nt & 1)*2 + 1]);
        }
    }

    #pragma unroll
    for (int mt = 0; mt < MT; mt++){
        int r0 = bm + wm + mt*16 + g;
        #pragma unroll
        for (int nt = 0; nt < 4; nt++){
            int cl = bn + wn + nt*8 + 2*tg;
            #pragma unroll
            for (int i = 0; i < 4; i++){
                int rr = r0 + (i >> 1)*8;
                int cc = cl + (i & 1);
                if (cc >= N) continue;
                float v = acc[mt][nt][i];
                size_t idx = (size_t)rr*ldc + cc;
                if (mode == 1){
                    v += C[idx];
                } else if (mode == 2){
                    float xv = v + bias[cc];
                    v = fmaxf(xv, 0.f) + log1pf(expf(-fabsf(xv)));
                }
                C[idx] = v;
            }
        }
    }
}

#define SMEMH4 (NSTG*(128+128)*SROW*sizeof(__half))   // 110592
#define SMEMH2 (NSTG*(64 +128)*SROW*sizeof(__half))   // 82944

// ---------------- split-K reductions (deterministic fixed order) ----------------
__global__ void k_reddbc(){
    int i = blockIdx.x*blockDim.x + threadIdx.x;
    if (i >= NR*DBCN) return;
    int r = i / DBCN, c = i % DBCN;
    float s = 0.f;
    #pragma unroll
    for (int z = 0; z < SPL_DBC; z++)
        s += g_split[(size_t)z*NR*DBCP + (size_t)r*DBCP + c];
    g_dbc[(size_t)r*DBCP + c] = s;
    if (c < DTR) h_dbc[(size_t)r*DTKP + c] = __float2half(s);
}

__global__ void k_redlm(){
    int i = blockIdx.x*blockDim.x + threadIdx.x;
    if (i >= NR*VOC) return;
    float s = 0.f;
    #pragma unroll
    for (int z = 0; z < SPL_LM; z++)
        s += g_split[(size_t)z*NR*VOC + i];
    g_logit[i] = s;
}

__global__ void k_redout(){
    int i = blockIdx.x*blockDim.x + threadIdx.x;
    if (i >= NR*DM) return;
    g_h[i] += g_split[i] + g_split[(size_t)NR*DM + i] + g_split[(size_t)2*NR*DM + i];
}

// ---------------- vectorized fp32 -> padded fp16 ----------------
__global__ void k_cvt2(const float* __restrict__ src, __half* __restrict__ dst,
                       int K, int KP){
    int r = blockIdx.x;
    const float2* s = (const float2*)(src + (size_t)r*K);
    __half* d = dst + (size_t)r*KP;
    const int n2 = K >> 1;
    for (int i = threadIdx.x; i < n2; i += blockDim.x){
        float2 v = s[i];
        *(__half2*)(d + 2*i) = __floats2half2_rn(v.x, v.y);
    }
}

__global__ void k_cvtw(const float* __restrict__ src, __half* __restrict__ dst,
                       int K, int KP, int n){
    int i = blockIdx.x*blockDim.x + threadIdx.x;
    if (i < n) dst[(size_t)(i/K)*KP + (i%K)] = __float2half(src[i]);
}

// ---------------- input transpose ----------------
__global__ void k_transpose_in(const float* __restrict__ x){
    int i = blockIdx.x*blockDim.x + threadIdx.x;
    if (i >= NR*DM) return;
    int n = i / DM, d = i % DM;
    int c = d / 25, r = d % 25, f = r / 5, e = r % 5;
    g_h[i] = x[((n*5 + f)*62 + c)*5 + e];
}

// ---------------- rmsnorm: g_h -> h_xn (fp16, padded) ----------------
__global__ void k_rmsnorm(const float* __restrict__ w){
    __shared__ float sh[33];
    int n = blockIdx.x;
    const float* row = g_h + (size_t)n*DM;
    float ss = 0.f;
    for (int d = threadIdx.x; d < DM; d += blockDim.x){ float v = row[d]; ss += v*v; }
    for (int o = 16; o; o >>= 1) ss += __shfl_down_sync(0xffffffffu, ss, o);
    if ((threadIdx.x & 31) == 0) sh[threadIdx.x >> 5] = ss;
    __syncthreads();
    if (threadIdx.x < 32){
        float v = (threadIdx.x < (int)(blockDim.x >> 5)) ? sh[threadIdx.x] : 0.f;
        for (int o = 16; o; o >>= 1) v += __shfl_down_sync(0xffffffffu, v, o);
        if (threadIdx.x == 0) sh[32] = rsqrtf(v / (float)DM + EPSF);
    }
    __syncthreads();
    float sc = sh[32];
    for (int d = threadIdx.x; d < DM; d += blockDim.x)
        h_xn[(size_t)n*DMP + d] = __float2half(row[d] * sc * w[d]);
}

// ---------------- depthwise causal conv + silu ----------------
__global__ void k_conv_silu(const float* __restrict__ cw, const float* __restrict__ cb){
    int e = blockIdx.x*blockDim.x + threadIdx.x;
    int b = blockIdx.y;
    if (e >= ED) return;
    size_t r0 = (size_t)(b*SEQ + 0)*(2*ED);
    size_t r1 = (size_t)(b*SEQ + 1)*(2*ED);
    size_t r2 = (size_t)(b*SEQ + 2)*(2*ED);
    float x0 = g_xz[r0 + e], x1 = g_xz[r1 + e], x2 = g_xz[r2 + e];
    float w1 = cw[e*4+1], w2 = cw[e*4+2], w3 = cw[e*4+3];
    float bb = cb[e];
    float y0 = siluf(bb + w3*x0);
    float y1 = siluf(bb + w2*x0 + w3*x1);
    float y2 = siluf(bb + w1*x0 + w2*x1 + w3*x2);
    g_xc[(size_t)(b*SEQ + 0)*ED + e] = y0;  h_xct[(size_t)(b*SEQ + 0)*EDP + e] = __float2half(y0);
    g_xc[(size_t)(b*SEQ + 1)*ED + e] = y1;  h_xct[(size_t)(b*SEQ + 1)*EDP + e] = __float2half(y1);
    g_xc[(size_t)(b*SEQ + 2)*ED + e] = y2;  h_xct[(size_t)(b*SEQ + 2)*EDP + e] = __float2half(y2);
}

// ---------------- negA (both layers) ----------------
__global__ void k_negA(const float* __restrict__ Alog){
    int i = blockIdx.x*blockDim.x + threadIdx.x;
    if (i < 2*ED*DS) g_negA[i] = -expf(Alog[i]);
}

// ---------------- fused SSM scan: block = e-slice, loops 16 batches ----------------
#define SCAN_BB 16
__global__ void k_scan(const float* __restrict__ nAbase, const float* __restrict__ Dp){
    __shared__ float sB[SEQ][DS], sC[SEQ][DS];
    int e = blockIdx.x*blockDim.x + threadIdx.x;
    int t = threadIdx.x;
    bool act = (e < ED);

    float nA[DS], dpe = 0.f;
    if (act){
        #pragma unroll
        for (int n = 0; n < DS; n++) nA[n] = nAbase[e*DS + n];
        dpe = Dp[e];
    }

    for (int bb = 0; bb < SCAN_BB; bb++){
        int b = blockIdx.y*SCAN_BB + bb;
        if (t < SEQ*DS){
            int s = t / DS, n = t % DS;
            size_t base = (size_t)(b*SEQ + s)*DBCP + DTR;
            sB[s][n] = g_dbc[base + n];
            sC[s][n] = g_dbc[base + DS + n];
        }
        __syncthreads();
        if (act){
            float hst[DS];
            #pragma unroll
            for (int n = 0; n < DS; n++) hst[n] = 0.f;
            #pragma unroll
            for (int s = 0; s < SEQ; s++){
                size_t row = (size_t)(b*SEQ + s);
                float d   = g_delta[row*ED + e];
                float xcv = g_xc[row*ED + e];
                float dx  = d * xcv;
                float y = 0.f;
                #pragma unroll
                for (int n = 0; n < DS; n++){
                    float dA = __expf(d * nA[n]);
                    hst[n] = dA*hst[n] + dx*sB[s][n];
                    y = fmaf(hst[n], sC[s][n], y);
                }
                y += dpe * xcv;
                float z = g_xz[row*(2*ED) + ED + e];
                h_ys[row*EDP + e] = __float2half(y * siluf(z));
            }
        }
        __syncthreads();
    }
}

// ---------------- logits mean/var (deterministic 2-pass) ----------------
__global__ void k_red1(){
    __shared__ float s1[32], s2[32];
    int base = blockIdx.x * 1024;
    float s = 0.f, q = 0.f;
    for (int i = threadIdx.x; i < 1024; i += 256){
        float v = g_logit[base + i];
        s += v; q += v*v;
    }
    for (int o = 16; o; o >>= 1){
        s += __shfl_down_sync(0xffffffffu, s, o);
        q += __shfl_down_sync(0xffffffffu, q, o);
    }
    if ((threadIdx.x & 31) == 0){ s1[threadIdx.x>>5] = s; s2[threadIdx.x>>5] = q; }
    __syncthreads();
    if (threadIdx.x < 32){
        float a = (threadIdx.x < 8) ? s1[threadIdx.x] : 0.f;
        float c = (threadIdx.x < 8) ? s2[threadIdx.x] : 0.f;
        for (int o = 4; o; o >>= 1){
            a += __shfl_down_sync(0xffffffffu, a, o);
            c += __shfl_down_sync(0xffffffffu, c, o);
        }
        if (threadIdx.x == 0){ g_part[blockIdx.x*2] = a; g_part[blockIdx.x*2+1] = c; }
    }
}

__global__ void k_red2(){
    __shared__ float s1[32], s2[32];
    float s = 0.f, q = 0.f;
    for (int i = threadIdx.x; i < 192; i += 256){ s += g_part[i*2]; q += g_part[i*2+1]; }
    for (int o = 16; o; o >>= 1){
        s += __shfl_down_sync(0xffffffffu, s, o);
        q += __shfl_down_sync(0xffffffffu, q, o);
    }
    if ((threadIdx.x & 31) == 0){ s1[threadIdx.x>>5] = s; s2[threadIdx.x>>5] = q; }
    __syncthreads();
    if (threadIdx.x == 0){
        float a = 0.f, c = 0.f;
        for (int i = 0; i < 8; i++){ a += s1[i]; c += s2[i]; }
        const float T = (float)(NR*VOC);
        float mean = a / T;
        float var  = c / T - mean*mean;
        g_stats[0] = mean;
        g_stats[1] = rsqrtf(var + EPSF);
    }
}

__global__ void k_nrm(){
    int i = blockIdx.x*blockDim.x + threadIdx.x;
    if (i < NR*VOC) h_nrm[i] = __float2half((g_logit[i] - g_stats[0]) * g_stats[1]);
}

__global__ void k_wesum(const float* __restrict__ emb_w){
    int o = threadIdx.x;
    float s = 0.f;
    for (int v = 0; v < VOC; v++) s += emb_w[o*VOC + v];
    g_wesum[o] = s;
}

// ---------------- final expand over f ----------------
__global__ void k_final(const float* __restrict__ bnw, const float* __restrict__ bnb,
                        const float* __restrict__ embb, float* __restrict__ out){
    int i = blockIdx.x*blockDim.x + threadIdx.x;
    const int total = BSZ*5*SEQ*OE;
    if (i >= total) return;
    int o = i & 255;
    int s = (i >> 8) % SEQ;
    int f = (i / (OE*SEQ)) % 5;
    int b = i / (OE*SEQ*5);
    int n = b*SEQ + s;
    out[i] = bnw[f]*g_t[(size_t)n*OE + o] + bnb[f]*g_wesum[o] + embb[o];
}

// ---------------- launch ----------------
extern "C" void kernel_launch(void* const* d_in, const int* in_sizes, int n_in,
                              void* d_out, int out_size)
{
    const float* x        = (const float*)d_in[0];
    const float* in_w     = (const float*)d_in[1];
    const float* conv_w   = (const float*)d_in[2];
    const float* conv_b   = (const float*)d_in[3];
    const float* xp_w     = (const float*)d_in[4];
    const float* dt_w     = (const float*)d_in[5];
    const float* dt_b     = (const float*)d_in[6];
    const float* A_log    = (const float*)d_in[7];
    const float* D_param  = (const float*)d_in[8];
    const float* out_w    = (const float*)d_in[9];
    const float* norm_w   = (const float*)d_in[10];
    const float* normf_w  = (const float*)d_in[11];
    const float* lm_w     = (const float*)d_in[12];
    const float* bn_w     = (const float*)d_in[13];
    const float* bn_b     = (const float*)d_in[14];
    const float* emb_w    = (const float*)d_in[15];
    const float* emb_b    = (const float*)d_in[16];
    float* out = (float*)d_out;

    cudaFuncSetAttribute(k_hmma<4>, cudaFuncAttributeMaxDynamicSharedMemorySize, (int)SMEMH4);
    cudaFuncSetAttribute(k_hmma<2>, cudaFuncAttributeMaxDynamicSharedMemorySize, (int)SMEMH2);

    float *pxz, *pdelta, *ph, *plog, *pt, *pnegA, *psplit;
    __half *qxn, *qinw, *qxct, *qxpw, *qdbc, *qdtw, *qys, *qoutw, *qlmw, *qnrm, *qembw;
    cudaGetSymbolAddress((void**)&ph,     g_h);
    cudaGetSymbolAddress((void**)&pxz,    g_xz);
    cudaGetSymbolAddress((void**)&pdelta, g_delta);
    cudaGetSymbolAddress((void**)&plog,   g_logit);
    cudaGetSymbolAddress((void**)&pt,     g_t);
    cudaGetSymbolAddress((void**)&pnegA,  g_negA);
    cudaGetSymbolAddress((void**)&psplit, g_split);
    cudaGetSymbolAddress((void**)&qxn,    h_xn);
    cudaGetSymbolAddress((void**)&qinw,   h_inw);
    cudaGetSymbolAddress((void**)&qxct,   h_xct);
    cudaGetSymbolAddress((void**)&qxpw,   h_xpw);
    cudaGetSymbolAddress((void**)&qdbc,   h_dbc);
    cudaGetSymbolAddress((void**)&qdtw,   h_dtw);
    cudaGetSymbolAddress((void**)&qys,    h_ys);
    cudaGetSymbolAddress((void**)&qoutw,  h_outw);
    cudaGetSymbolAddress((void**)&qlmw,   h_lmw);
    cudaGetSymbolAddress((void**)&qnrm,   h_nrm);
    cudaGetSymbolAddress((void**)&qembw,  h_embw);

    // launches 0..3: profiled launch (index 3) = in_proj GEMM (k_hmma<4>)
    k_transpose_in<<<(NR*DM + 255)/256, 256>>>(x);                          // 0
    k_cvt2<<<2*2*ED, 256>>>(in_w, qinw, DM, DMP);                           // 1
    k_rmsnorm<<<NR, 256>>>(norm_w);                                         // 2
    k_hmma<4><<<dim3(49, 12), 256, SMEMH4>>>(                               // 3 <- profiled
        qxn, DMP, qinw, DMP, pxz, 2*ED, NR, 2*ED, DMP, DMP, 0, nullptr);

    // remaining weight conversions
    k_cvt2<<<2*DM, 256>>>(out_w, qoutw, ED, EDP);
    k_cvt2<<<2*DBCN, 256>>>(xp_w, qxpw, ED, EDP);
    k_cvtw<<<(2*ED*DTR + 255)/256, 256>>>(dt_w, qdtw, DTR, DTKP, 2*ED*DTR);
    k_negA<<<(2*ED*DS + 255)/256, 256>>>(A_log);

    for (int l = 0; l < 2; l++){
        if (l == 1){
            k_rmsnorm<<<NR, 256>>>(norm_w + DM);
            k_hmma<4><<<dim3(49, 12), 256, SMEMH4>>>(
                qxn, DMP, qinw + (size_t)2*ED*DMP, DMP, pxz, 2*ED, NR, 2*ED, DMP, DMP, 0, nullptr);
        }
        k_conv_silu<<<dim3((ED+255)/256, BSZ), 256>>>(conv_w + (size_t)l*ED*4, conv_b + l*ED);
        // dbc partials: xct @ xp_w^T  (1536 x 129, K=3136, split-K 7 x 448)
        k_hmma<2><<<dim3(2, 24, SPL_DBC), 256, SMEMH2>>>(
            qxct, EDP, qxpw + (size_t)l*DBCN*EDP, EDP, psplit, DBCP, NR, DBCN, EDP, 448, 4, nullptr);
        k_reddbc<<<(NR*DBCN + 255)/256, 256>>>();
        // delta = softplus(dt @ dtw^T + dt_b)  (1536 x 3100, K=128)
        k_hmma<4><<<dim3(25, 12), 256, SMEMH4>>>(
            qdbc, DTKP, qdtw + (size_t)l*ED*DTKP, DTKP, pdelta, ED, NR, ED, DTKP, DTKP, 2, dt_b + l*ED);
        // scan -> h_ys
        k_scan<<<dim3((ED+255)/256, BSZ/SCAN_BB), 256>>>(pnegA + (size_t)l*ED*DS, D_param + l*ED);
        // out_proj partials: ys @ out_w^T (1536 x 1550, K=3136, split-K 3 x 1088), then h +=
        k_hmma<4><<<dim3(13, 12, SPL_OUT), 256, SMEMH4>>>(
            qys, EDP, qoutw + (size_t)l*DM*EDP, EDP, psplit, DM, NR, DM, EDP, 1088, 4, nullptr);
        k_redout<<<(NR*DM + 255)/256, 256>>>();
    }

    k_rmsnorm<<<NR, 256>>>(normf_w);
    k_cvt2<<<VOC, 256>>>(lm_w, qlmw, DM, DMP);
    // logits partials: xn @ lm_w^T  (1536 x 128, K=1600, split-K 5 x 320)
    k_hmma<2><<<dim3(1, 24, SPL_LM), 256, SMEMH2>>>(
        qxn, DMP, qlmw, DMP, psplit, VOC, NR, VOC, DMP, 320, 4, nullptr);
    k_redlm<<<(NR*VOC + 255)/256, 256>>>();
    k_red1<<<192, 256>>>();
    k_red2<<<1, 256>>>();
    k_nrm<<<(NR*VOC + 255)/256, 256>>>();
    k_cvt2<<<OE, 256>>>(emb_w, qembw, VOC, VOC);
    // t = nrm @ emb_w^T  (1536 x 256, K=128)
    k_hmma<2><<<dim3(2, 24), 256, SMEMH2>>>(
        qnrm, VOC, qembw, VOC, pt, OE, NR, OE, VOC, VOC, 0, nullptr);
    k_wesum<<<1, 256>>>(emb_w);
    k_final<<<(BSZ*5*SEQ*OE + 255)/256, 256>>>(bn_w, bn_b, emb_b, out);
}

// round 14
// speedup vs baseline: 1.2640x; 1.0234x over previous
#include <cuda_runtime.h>
#include <cuda_fp16.h>
#include <math.h>
#include <stdint.h>

// ---------------- problem constants ----------------
#define BSZ   512
#define SEQ   3
#define DM    1550
#define DMP   1600          // DM padded to x64
#define DS    16
#define ED    3100
#define EDP   3136          // ED padded to x64
#define DTR   97
#define DTKP  128           // dt GEMM K padded
#define DBCN  129
#define DBCP  132           // fp32 dbc ldc
#define VOC   128
#define NR    (BSZ*SEQ)
#define OE    256
#define EPSF  1e-5f

#define SROW  72            // smem row stride in halves (BK=64 + 8 pad)
#define NSTG  3

#define SPL_DBC 6           // dbc split-K (5 x 576 + 256 = 3136)
#define KS_DBC  576
#define SPL_LM  5           // lm  split-K (5 x 320 = 1600)
#define KS_LM   320
#define SPL_OUT 4           // out split-K (3 x 832 + 640 = 3136)
#define KS_OUT  832

// ---------------- fp32 scratch ----------------
__device__ __align__(256) float g_h    [NR*DM];
__device__ __align__(256) float g_xz   [NR*2*ED];
__device__ __align__(256) float g_xc   [NR*ED];
__device__ __align__(256) float g_dbc  [NR*DBCP];
__device__ __align__(256) float g_delta[NR*ED];
__device__ __align__(256) float g_negA [2*ED*DS];
__device__ __align__(256) float g_logit[NR*VOC];
__device__ __align__(256) float g_t    [NR*OE];
__device__ __align__(256) float g_split[4*NR*DM];   // split-K partials (38MB, covers all uses)
__device__ float g_part [384];
__device__ float g_stats[2];
__device__ float g_wesum[OE];

// ---------------- fp16 GEMM operand scratch (zero-init pads) ----------------
__device__ __align__(256) __half h_xn  [NR*DMP];
__device__ __align__(256) __half h_inw [2*2*ED*DMP];
__device__ __align__(256) __half h_xct [NR*EDP];
__device__ __align__(256) __half h_xpw [2*DBCN*EDP];
__device__ __align__(256) __half h_dbc [NR*DTKP];
__device__ __align__(256) __half h_dtw [2*ED*DTKP];
__device__ __align__(256) __half h_ys  [NR*EDP];
__device__ __align__(256) __half h_outw[2*DM*EDP];
__device__ __align__(256) __half h_lmw [VOC*DMP];
__device__ __align__(256) __half h_nrm [NR*VOC];
__device__ __align__(256) __half h_embw[OE*VOC];

__device__ __forceinline__ float siluf(float v){ return v / (1.f + expf(-v)); }

__device__ __forceinline__ void mma_f16(float c[4],
    uint32_t a0, uint32_t a1, uint32_t a2, uint32_t a3,
    uint32_t b0, uint32_t b1)
{
    asm volatile(
        "mma.sync.aligned.m16n8k16.row.col.f32.f16.f16.f32 "
        "{%0,%1,%2,%3}, {%4,%5,%6,%7}, {%8,%9}, {%0,%1,%2,%3};"
        : "+f"(c[0]), "+f"(c[1]), "+f"(c[2]), "+f"(c[3])
        : "r"(a0), "r"(a1), "r"(a2), "r"(a3), "r"(b0), "r"(b1));
}

__device__ __forceinline__ void cpa16(uint32_t sdst, const __half* gsrc, int nbytes){
    asm volatile("cp.async.cg.shared.global [%0], [%1], 16, %2;"
                 :: "r"(sdst), "l"(gsrc), "r"(nbytes));
}

__device__ __forceinline__ void ldsm4(uint32_t r[4], uint32_t addr){
    asm volatile("ldmatrix.sync.aligned.m8n8.x4.shared.b16 {%0,%1,%2,%3}, [%4];"
        : "=r"(r[0]), "=r"(r[1]), "=r"(r[2]), "=r"(r[3]) : "r"(addr));
}

// ---------------- k_hmma: 8-warp 2x4 GEMM, optional split-K ----------------
// gk range [z*KS, min(K, (z+1)*KS)). mode 0: C = acc ; 1: C += acc ;
// 2: softplus(acc+bias) ; 4: partial write to C + z*M*ldc.
template<int MT>
__global__ void __launch_bounds__(256, 2) k_hmma(
    const __half* __restrict__ A, int lda,
    const __half* __restrict__ B, int ldb,
    float* __restrict__ C, int ldc,
    int M, int N, int K, int KS,
    int mode, const float* __restrict__ bias)
{
    constexpr int BM = MT*32;
    extern __shared__ __half smh[];
    __half* As = smh;
    __half* Bs = smh + NSTG*BM*SROW;

    const int tid  = threadIdx.x;
    const int wid  = tid >> 5, lane = tid & 31;
    const int g    = lane >> 2, tg = lane & 3;
    const int wm   = (wid >> 2) * (MT*16);
    const int wn   = (wid & 3) * 32;
    const int bm   = blockIdx.y * BM;
    const int bn   = blockIdx.x * 128;
    const int lrow = tid >> 3;
    const int lcol = (tid & 7) * 8;
    const int k0   = blockIdx.z * KS;
    const int nch  = (((K - k0) < KS ? (K - k0) : KS)) >> 6;
    if (mode == 4) C += (size_t)blockIdx.z * (size_t)M * ldc;

    const uint32_t sA = (uint32_t)__cvta_generic_to_shared(As);
    const uint32_t sB = (uint32_t)__cvta_generic_to_shared(Bs);

    uint32_t aaddr[MT], baddr[2];
    {
        int arow = wm + (lane & 15);
        int acol = ((lane >> 4) & 1) * 8;
        #pragma unroll
        for (int mt = 0; mt < MT; mt++)
            aaddr[mt] = sA + (uint32_t)(((arow + mt*16)*SROW + acol)*2);
        #pragma unroll
        for (int ntp = 0; ntp < 2; ntp++){
            int brow = wn + ntp*16 + (lane & 7) + ((lane >> 4) & 1)*8;
            int bcol = ((lane >> 3) & 1) * 8;
            baddr[ntp] = sB + (uint32_t)((brow*SROW + bcol)*2);
        }
    }

    float acc[MT][4][4];
    #pragma unroll
    for (int mt = 0; mt < MT; mt++)
        #pragma unroll
        for (int nt = 0; nt < 4; nt++)
            #pragma unroll
            for (int i = 0; i < 4; i++) acc[mt][nt][i] = 0.f;

    auto issue = [&](int c){
        const int gk = k0 + c*64 + lcol;
        const int s  = c % NSTG;
        uint32_t da = sA + (uint32_t)((s*BM*SROW + lrow*SROW + lcol)*2);
        #pragma unroll
        for (int p = 0; p < BM/32; p++)
            cpa16(da + (uint32_t)(p*32*SROW*2),
                  A + (size_t)(bm + lrow + p*32)*lda + gk, 16);
        uint32_t db = sB + (uint32_t)((s*128*SROW + lrow*SROW + lcol)*2);
        #pragma unroll
        for (int p = 0; p < 4; p++){
            int gn = bn + lrow + p*32;
            cpa16(db + (uint32_t)(p*32*SROW*2),
                  B + (size_t)(gn < N ? gn : 0)*ldb + gk, (gn < N) ? 16 : 0);
        }
        asm volatile("cp.async.commit_group;");
    };

    issue(0);
    issue(1);
    for (int c = 0; c < nch; c++){
        if (c + 1 < nch) asm volatile("cp.async.wait_group 1;");
        else             asm volatile("cp.async.wait_group 0;");
        __syncthreads();
        if (c + 2 < nch) issue(c + 2);

        const uint32_t offA = (uint32_t)((c % NSTG)*BM*SROW*2);
        const uint32_t offB = (uint32_t)((c % NSTG)*128*SROW*2);
        #pragma unroll
        for (int kst = 0; kst < 4; kst++){
            uint32_t af[MT][4], bfr[2][4];
            #pragma unroll
            for (int mt = 0; mt < MT; mt++)
                ldsm4(af[mt], aaddr[mt] + offA + kst*32);
            #pragma unroll
            for (int ntp = 0; ntp < 2; ntp++)
                ldsm4(bfr[ntp], baddr[ntp] + offB + kst*32);
            #pragma unroll
            for (int mt = 0; mt < MT; mt++)
                #pragma unroll
                for (int nt = 0; nt < 4; nt++)
                    mma_f16(acc[mt][nt],
                            af[mt][0], af[mt][1], af[mt][2], af[mt][3],
                            bfr[nt >> 1][(nt & 1)*2], bfr[nt >> 1][(nt & 1)*2 + 1]);
        }
    }

    #pragma unroll
    for (int mt = 0; mt < MT; mt++){
        int r0 = bm + wm + mt*16 + g;
        #pragma unroll
        for (int nt = 0; nt < 4; nt++){
            int cl = bn + wn + nt*8 + 2*tg;
            #pragma unroll
            for (int i = 0; i < 4; i++){
                int rr = r0 + (i >> 1)*8;
                int cc = cl + (i & 1);
                if (cc >= N) continue;
                float v = acc[mt][nt][i];
                size_t idx = (size_t)rr*ldc + cc;
                if (mode == 1){
                    v += C[idx];
                } else if (mode == 2){
                    float xv = v + bias[cc];
                    v = fmaxf(xv, 0.f) + log1pf(expf(-fabsf(xv)));
                }
                C[idx] = v;
            }
        }
    }
}

#define SMEMH4 (NSTG*(128+128)*SROW*sizeof(__half))   // 110592
#define SMEMH2 (NSTG*(64 +128)*SROW*sizeof(__half))   // 82944

// ---------------- fused split-K reduce ----------------
__global__ void k_reddbc(){
    int i = blockIdx.x*blockDim.x + threadIdx.x;
    if (i >= NR*DBCN) return;
    int r = i / DBCN, c = i % DBCN;
    float s = 0.f;
    #pragma unroll
    for (int z = 0; z < SPL_DBC; z++)
        s += g_split[(size_t)z*NR*DBCP + (size_t)r*DBCP + c];
    g_dbc[(size_t)r*DBCP + c] = s;
    if (c < DTR) h_dbc[(size_t)r*DTKP + c] = __float2half(s);
}

// fused: h += sum of SPL_OUT partials, then rmsnorm(h, w) -> h_xn
__global__ void k_redout_norm(const float* __restrict__ w){
    __shared__ float sh[33];
    int n = blockIdx.x;
    float ss = 0.f;
    for (int d = threadIdx.x; d < DM; d += blockDim.x){
        size_t idx = (size_t)n*DM + d;
        float v = g_h[idx];
        #pragma unroll
        for (int z = 0; z < SPL_OUT; z++)
            v += g_split[(size_t)z*NR*DM + idx];
        g_h[idx] = v;
        ss += v*v;
    }
    for (int o = 16; o; o >>= 1) ss += __shfl_down_sync(0xffffffffu, ss, o);
    if ((threadIdx.x & 31) == 0) sh[threadIdx.x >> 5] = ss;
    __syncthreads();
    if (threadIdx.x < 32){
        float v = (threadIdx.x < (int)(blockDim.x >> 5)) ? sh[threadIdx.x] : 0.f;
        for (int o = 16; o; o >>= 1) v += __shfl_down_sync(0xffffffffu, v, o);
        if (threadIdx.x == 0) sh[32] = rsqrtf(v / (float)DM + EPSF);
    }
    __syncthreads();
    float sc = sh[32];
    for (int d = threadIdx.x; d < DM; d += blockDim.x)
        h_xn[(size_t)n*DMP + d] = __float2half(g_h[(size_t)n*DM + d] * sc * w[d]);
}

// fused: logits = sum of SPL_LM partials + per-block sum/sumsq for batchnorm stats
__global__ void k_redlm_red1(){
    __shared__ float s1[32], s2[32];
    int base = blockIdx.x * 1024;
    float s = 0.f, q = 0.f;
    for (int i = threadIdx.x; i < 1024; i += 256){
        float v = 0.f;
        #pragma unroll
        for (int z = 0; z < SPL_LM; z++)
            v += g_split[(size_t)z*NR*VOC + base + i];
        g_logit[base + i] = v;
        s += v; q += v*v;
    }
    for (int o = 16; o; o >>= 1){
        s += __shfl_down_sync(0xffffffffu, s, o);
        q += __shfl_down_sync(0xffffffffu, q, o);
    }
    if ((threadIdx.x & 31) == 0){ s1[threadIdx.x>>5] = s; s2[threadIdx.x>>5] = q; }
    __syncthreads();
    if (threadIdx.x < 32){
        float a = (threadIdx.x < 8) ? s1[threadIdx.x] : 0.f;
        float c = (threadIdx.x < 8) ? s2[threadIdx.x] : 0.f;
        for (int o = 4; o; o >>= 1){
            a += __shfl_down_sync(0xffffffffu, a, o);
            c += __shfl_down_sync(0xffffffffu, c, o);
        }
        if (threadIdx.x == 0){ g_part[blockIdx.x*2] = a; g_part[blockIdx.x*2+1] = c; }
    }
}

// final stats + wesum (single block)
__global__ void k_red2_wesum(const float* __restrict__ emb_w){
    __shared__ float s1[32], s2[32];
    float s = 0.f, q = 0.f;
    for (int i = threadIdx.x; i < 192; i += 256){ s += g_part[i*2]; q += g_part[i*2+1]; }
    for (int o = 16; o; o >>= 1){
        s += __shfl_down_sync(0xffffffffu, s, o);
        q += __shfl_down_sync(0xffffffffu, q, o);
    }
    if ((threadIdx.x & 31) == 0){ s1[threadIdx.x>>5] = s; s2[threadIdx.x>>5] = q; }
    __syncthreads();
    if (threadIdx.x == 0){
        float a = 0.f, c = 0.f;
        for (int i = 0; i < 8; i++){ a += s1[i]; c += s2[i]; }
        const float T = (float)(NR*VOC);
        float mean = a / T;
        float var  = c / T - mean*mean;
        g_stats[0] = mean;
        g_stats[1] = rsqrtf(var + EPSF);
    }
    // wesum: 256 threads, one output row each
    float ws = 0.f;
    for (int v = 0; v < VOC; v++) ws += emb_w[threadIdx.x*VOC + v];
    g_wesum[threadIdx.x] = ws;
}

// ---------------- vectorized fp32 -> padded fp16 ----------------
__global__ void k_cvt2(const float* __restrict__ src, __half* __restrict__ dst,
                       int K, int KP){
    int r = blockIdx.x;
    const float2* s = (const float2*)(src + (size_t)r*K);
    __half* d = dst + (size_t)r*KP;
    const int n2 = K >> 1;
    for (int i = threadIdx.x; i < n2; i += blockDim.x){
        float2 v = s[i];
        *(__half2*)(d + 2*i) = __floats2half2_rn(v.x, v.y);
    }
}

__global__ void k_cvtw(const float* __restrict__ src, __half* __restrict__ dst,
                       int K, int KP, int n){
    int i = blockIdx.x*blockDim.x + threadIdx.x;
    if (i < n) dst[(size_t)(i/K)*KP + (i%K)] = __float2half(src[i]);
}

// ---------------- fused input transpose + rmsnorm(layer0) ----------------
// x row n is contiguous [1550]; h[n, c*25+f*5+e] = x[n, (f*62+c)*5+e].
__global__ void k_trans_norm(const float* __restrict__ x, const float* __restrict__ w){
    __shared__ float sm[DM];
    __shared__ float sh[33];
    int n = blockIdx.x;
    const float* row = x + (size_t)n*DM;
    float ss = 0.f;
    for (int d = threadIdx.x; d < DM; d += blockDim.x){
        float v = row[d];
        sm[d] = v;
        ss += v*v;
    }
    for (int o = 16; o; o >>= 1) ss += __shfl_down_sync(0xffffffffu, ss, o);
    if ((threadIdx.x & 31) == 0) sh[threadIdx.x >> 5] = ss;
    __syncthreads();
    if (threadIdx.x < 32){
        float v = (threadIdx.x < (int)(blockDim.x >> 5)) ? sh[threadIdx.x] : 0.f;
        for (int o = 16; o; o >>= 1) v += __shfl_down_sync(0xffffffffu, v, o);
        if (threadIdx.x == 0) sh[32] = rsqrtf(v / (float)DM + EPSF);
    }
    __syncthreads();
    float sc = sh[32];
    for (int d = threadIdx.x; d < DM; d += blockDim.x){
        int c = d / 25, r = d % 25, f = r / 5, e = r % 5;
        float v = sm[(f*62 + c)*5 + e];
        g_h[(size_t)n*DM + d] = v;
        h_xn[(size_t)n*DMP + d] = __float2half(v * sc * w[d]);
    }
}

// ---------------- depthwise causal conv + silu ----------------
__global__ void k_conv_silu(const float* __restrict__ cw, const float* __restrict__ cb){
    int e = blockIdx.x*blockDim.x + threadIdx.x;
    int b = blockIdx.y;
    if (e >= ED) return;
    size_t r0 = (size_t)(b*SEQ + 0)*(2*ED);
    size_t r1 = (size_t)(b*SEQ + 1)*(2*ED);
    size_t r2 = (size_t)(b*SEQ + 2)*(2*ED);
    float x0 = g_xz[r0 + e], x1 = g_xz[r1 + e], x2 = g_xz[r2 + e];
    float w1 = cw[e*4+1], w2 = cw[e*4+2], w3 = cw[e*4+3];
    float bb = cb[e];
    float y0 = siluf(bb + w3*x0);
    float y1 = siluf(bb + w2*x0 + w3*x1);
    float y2 = siluf(bb + w1*x0 + w2*x1 + w3*x2);
    g_xc[(size_t)(b*SEQ + 0)*ED + e] = y0;  h_xct[(size_t)(b*SEQ + 0)*EDP + e] = __float2half(y0);
    g_xc[(size_t)(b*SEQ + 1)*ED + e] = y1;  h_xct[(size_t)(b*SEQ + 1)*EDP + e] = __float2half(y1);
    g_xc[(size_t)(b*SEQ + 2)*ED + e] = y2;  h_xct[(size_t)(b*SEQ + 2)*EDP + e] = __float2half(y2);
}

// ---------------- negA (both layers) ----------------
__global__ void k_negA(const float* __restrict__ Alog){
    int i = blockIdx.x*blockDim.x + threadIdx.x;
    if (i < 2*ED*DS) g_negA[i] = -expf(Alog[i]);
}

// ---------------- fused SSM scan: block = e-slice, loops 16 batches ----------------
#define SCAN_BB 16
__global__ void k_scan(const float* __restrict__ nAbase, const float* __restrict__ Dp){
    __shared__ float sB[SEQ][DS], sC[SEQ][DS];
    int e = blockIdx.x*blockDim.x + threadIdx.x;
    int t = threadIdx.x;
    bool act = (e < ED);

    float nA[DS], dpe = 0.f;
    if (act){
        #pragma unroll
        for (int n = 0; n < DS; n++) nA[n] = nAbase[e*DS + n];
        dpe = Dp[e];
    }

    for (int bb = 0; bb < SCAN_BB; bb++){
        int b = blockIdx.y*SCAN_BB + bb;
        if (t < SEQ*DS){
            int s = t / DS, n = t % DS;
            size_t base = (size_t)(b*SEQ + s)*DBCP + DTR;
            sB[s][n] = g_dbc[base + n];
            sC[s][n] = g_dbc[base + DS + n];
        }
        __syncthreads();
        if (act){
            float hst[DS];
            #pragma unroll
            for (int n = 0; n < DS; n++) hst[n] = 0.f;
            #pragma unroll
            for (int s = 0; s < SEQ; s++){
                size_t row = (size_t)(b*SEQ + s);
                float d   = g_delta[row*ED + e];
                float xcv = g_xc[row*ED + e];
                float dx  = d * xcv;
                float y = 0.f;
                #pragma unroll
                for (int n = 0; n < DS; n++){
                    float dA = __expf(d * nA[n]);
                    hst[n] = dA*hst[n] + dx*sB[s][n];
                    y = fmaf(hst[n], sC[s][n], y);
                }
                y += dpe * xcv;
                float z = g_xz[row*(2*ED) + ED + e];
                h_ys[row*EDP + e] = __float2half(y * siluf(z));
            }
        }
        __syncthreads();
    }
}

__global__ void k_nrm(){
    int i = blockIdx.x*blockDim.x + threadIdx.x;
    if (i < NR*VOC) h_nrm[i] = __float2half((g_logit[i] - g_stats[0]) * g_stats[1]);
}

// ---------------- final expand over f ----------------
__global__ void k_final(const float* __restrict__ bnw, const float* __restrict__ bnb,
                        const float* __restrict__ embb, float* __restrict__ out){
    int i = blockIdx.x*blockDim.x + threadIdx.x;
    const int total = BSZ*5*SEQ*OE;
    if (i >= total) return;
    int o = i & 255;
    int s = (i >> 8) % SEQ;
    int f = (i / (OE*SEQ)) % 5;
    int b = i / (OE*SEQ*5);
    int n = b*SEQ + s;
    out[i] = bnw[f]*g_t[(size_t)n*OE + o] + bnb[f]*g_wesum[o] + embb[o];
}

// ---------------- launch ----------------
extern "C" void kernel_launch(void* const* d_in, const int* in_sizes, int n_in,
                              void* d_out, int out_size)
{
    const float* x        = (const float*)d_in[0];
    const float* in_w     = (const float*)d_in[1];
    const float* conv_w   = (const float*)d_in[2];
    const float* conv_b   = (const float*)d_in[3];
    const float* xp_w     = (const float*)d_in[4];
    const float* dt_w     = (const float*)d_in[5];
    const float* dt_b     = (const float*)d_in[6];
    const float* A_log    = (const float*)d_in[7];
    const float* D_param  = (const float*)d_in[8];
    const float* out_w    = (const float*)d_in[9];
    const float* norm_w   = (const float*)d_in[10];
    const float* normf_w  = (const float*)d_in[11];
    const float* lm_w     = (const float*)d_in[12];
    const float* bn_w     = (const float*)d_in[13];
    const float* bn_b     = (const float*)d_in[14];
    const float* emb_w    = (const float*)d_in[15];
    const float* emb_b    = (const float*)d_in[16];
    float* out = (float*)d_out;

    cudaFuncSetAttribute(k_hmma<4>, cudaFuncAttributeMaxDynamicSharedMemorySize, (int)SMEMH4);
    cudaFuncSetAttribute(k_hmma<2>, cudaFuncAttributeMaxDynamicSharedMemorySize, (int)SMEMH2);

    float *pxz, *pdelta, *ph, *plog, *pt, *pnegA, *psplit;
    __half *qxn, *qinw, *qxct, *qxpw, *qdbc, *qdtw, *qys, *qoutw, *qlmw, *qnrm, *qembw;
    cudaGetSymbolAddress((void**)&ph,     g_h);
    cudaGetSymbolAddress((void**)&pxz,    g_xz);
    cudaGetSymbolAddress((void**)&pdelta, g_delta);
    cudaGetSymbolAddress((void**)&plog,   g_logit);
    cudaGetSymbolAddress((void**)&pt,     g_t);
    cudaGetSymbolAddress((void**)&pnegA,  g_negA);
    cudaGetSymbolAddress((void**)&psplit, g_split);
    cudaGetSymbolAddress((void**)&qxn,    h_xn);
    cudaGetSymbolAddress((void**)&qinw,   h_inw);
    cudaGetSymbolAddress((void**)&qxct,   h_xct);
    cudaGetSymbolAddress((void**)&qxpw,   h_xpw);
    cudaGetSymbolAddress((void**)&qdbc,   h_dbc);
    cudaGetSymbolAddress((void**)&qdtw,   h_dtw);
    cudaGetSymbolAddress((void**)&qys,    h_ys);
    cudaGetSymbolAddress((void**)&qoutw,  h_outw);
    cudaGetSymbolAddress((void**)&qlmw,   h_lmw);
    cudaGetSymbolAddress((void**)&qnrm,   h_nrm);
    cudaGetSymbolAddress((void**)&qembw,  h_embw);

    // launches 0..3: profiled launch (index 3) = in_proj GEMM (k_hmma<4>)
    k_trans_norm<<<NR, 256>>>(x, norm_w);                                   // 0
    k_cvt2<<<2*2*ED, 256>>>(in_w, qinw, DM, DMP);                           // 1
    k_cvt2<<<2*DM, 256>>>(out_w, qoutw, ED, EDP);                           // 2
    k_hmma<4><<<dim3(49, 12), 256, SMEMH4>>>(                               // 3 <- profiled
        qxn, DMP, qinw, DMP, pxz, 2*ED, NR, 2*ED, DMP, DMP, 0, nullptr);

    // remaining weight conversions
    k_cvt2<<<2*DBCN, 256>>>(xp_w, qxpw, ED, EDP);
    k_cvtw<<<(2*ED*DTR + 255)/256, 256>>>(dt_w, qdtw, DTR, DTKP, 2*ED*DTR);
    k_negA<<<(2*ED*DS + 255)/256, 256>>>(A_log);

    for (int l = 0; l < 2; l++){
        if (l == 1){
            // h_xn already produced by k_redout_norm(norm_w+DM)
            k_hmma<4><<<dim3(49, 12), 256, SMEMH4>>>(
                qxn, DMP, qinw + (size_t)2*ED*DMP, DMP, pxz, 2*ED, NR, 2*ED, DMP, DMP, 0, nullptr);
        }
        k_conv_silu<<<dim3((ED+255)/256, BSZ), 256>>>(conv_w + (size_t)l*ED*4, conv_b + l*ED);
        // dbc partials: xct @ xp_w^T  (1536 x 129, K=3136, split-K 6 x 576)
        k_hmma<2><<<dim3(2, 24, SPL_DBC), 256, SMEMH2>>>(
            qxct, EDP, qxpw + (size_t)l*DBCN*EDP, EDP, psplit, DBCP, NR, DBCN, EDP, KS_DBC, 4, nullptr);
        k_reddbc<<<(NR*DBCN + 255)/256, 256>>>();
        // delta = softplus(dt @ dtw^T + dt_b)  (1536 x 3100, K=128)
        k_hmma<4><<<dim3(25, 12), 256, SMEMH4>>>(
            qdbc, DTKP, qdtw + (size_t)l*ED*DTKP, DTKP, pdelta, ED, NR, ED, DTKP, DTKP, 2, dt_b + l*ED);
        // scan -> h_ys
        k_scan<<<dim3((ED+255)/256, BSZ/SCAN_BB), 256>>>(pnegA + (size_t)l*ED*DS, D_param + l*ED);
        // out_proj partials: ys @ out_w^T (1536 x 1550, K=3136, split-K 4 x 832)
        k_hmma<4><<<dim3(13, 12, SPL_OUT), 256, SMEMH4>>>(
            qys, EDP, qoutw + (size_t)l*DM*EDP, EDP, psplit, DM, NR, DM, EDP, KS_OUT, 4, nullptr);
        // fused: h += partials, rmsnorm -> h_xn (next layer's input / final norm)
        k_redout_norm<<<NR, 256>>>(l == 0 ? norm_w + DM : normf_w);
    }

    k_cvt2<<<VOC, 256>>>(lm_w, qlmw, DM, DMP);
    // logits partials: xn @ lm_w^T  (1536 x 128, K=1600, split-K 5 x 320)
    k_hmma<2><<<dim3(1, 24, SPL_LM), 256, SMEMH2>>>(
        qxn, DMP, qlmw, DMP, psplit, VOC, NR, VOC, DMP, KS_LM, 4, nullptr);
    // fused: reduce partials -> logits + block stats
    k_redlm_red1<<<192, 256>>>();
    k_red2_wesum<<<1, 256>>>(emb_w);
    k_nrm<<<(NR*VOC + 255)/256, 256>>>();
    k_cvt2<<<OE, 256>>>(emb_w, qembw, VOC, VOC);
    // t = nrm @ emb_w^T  (1536 x 256, K=128)
    k_hmma<2><<<dim3(2, 24), 256, SMEMH2>>>(
        qnrm, VOC, qembw, VOC, pt, OE, NR, OE, VOC, VOC, 0, nullptr);
    k_final<<<(BSZ*5*SEQ*OE + 255)/256, 256>>>(bn_w, bn_b, emb_b, out);
}

// round 16
// speedup vs baseline: 1.3062x; 1.0334x over previous
#include <cuda_runtime.h>
#include <cuda_fp16.h>
#include <math.h>
#include <stdint.h>

// ---------------- problem constants ----------------
#define BSZ   512
#define SEQ   3
#define DM    1550
#define DMP   1600          // DM padded to x64
#define DS    16
#define ED    3100
#define EDP   3136          // ED padded to x64
#define DTR   97
#define DTKP  128           // dt GEMM K padded
#define DBCN  129
#define DBCP  132           // fp32 dbc ldc
#define VOC   128
#define NR    (BSZ*SEQ)
#define OE    256
#define EPSF  1e-5f

#define SROW  72            // smem row stride in halves (BK=64 + 8 pad)
#define NSTG  3

#define SPL_DBC 6           // dbc split-K (5 x 576 + 256 = 3136)
#define KS_DBC  576
#define SPL_LM  5           // lm  split-K (5 x 320 = 1600)
#define KS_LM   320
#define SPL_OUT 4           // out split-K (3 x 832 + 640 = 3136)
#define KS_OUT  832

// ---------------- fp32 scratch ----------------
__device__ __align__(256) float g_h    [NR*DM];
__device__ __align__(256) float g_xz   [NR*2*ED];
__device__ __align__(256) float g_dbc  [NR*DBCP];
__device__ __align__(256) float g_delta[NR*ED];
__device__ __align__(256) float g_negA [2*ED*DS];
__device__ __align__(256) float g_logit[NR*VOC];
__device__ __align__(256) float g_t    [NR*OE];
__device__ __align__(256) float g_split[4*NR*DM];   // split-K partials
__device__ float g_part [384];
__device__ float g_stats[2];
__device__ float g_wesum[OE];

// ---------------- fp16 GEMM operand scratch (zero-init pads) ----------------
__device__ __align__(256) __half h_xn  [NR*DMP];
__device__ __align__(256) __half h_inw [2*2*ED*DMP];
__device__ __align__(256) __half h_xct [NR*EDP];
__device__ __align__(256) __half h_xpw [2*DBCN*EDP];
__device__ __align__(256) __half h_dbc [NR*DTKP];
__device__ __align__(256) __half h_dtw [2*ED*DTKP];
__device__ __align__(256) __half h_ys  [NR*EDP];
__device__ __align__(256) __half h_outw[2*DM*EDP];
__device__ __align__(256) __half h_lmw [VOC*DMP];
__device__ __align__(256) __half h_nrm [NR*VOC];
__device__ __align__(256) __half h_embw[OE*VOC];

__device__ __forceinline__ float siluf(float v){ return v / (1.f + expf(-v)); }

__device__ __forceinline__ void mma_f16(float c[4],
    uint32_t a0, uint32_t a1, uint32_t a2, uint32_t a3,
    uint32_t b0, uint32_t b1)
{
    asm volatile(
        "mma.sync.aligned.m16n8k16.row.col.f32.f16.f16.f32 "
        "{%0,%1,%2,%3}, {%4,%5,%6,%7}, {%8,%9}, {%0,%1,%2,%3};"
        : "+f"(c[0]), "+f"(c[1]), "+f"(c[2]), "+f"(c[3])
        : "r"(a0), "r"(a1), "r"(a2), "r"(a3), "r"(b0), "r"(b1));
}

__device__ __forceinline__ void cpa16(uint32_t sdst, const __half* gsrc, int nbytes){
    asm volatile("cp.async.cg.shared.global [%0], [%1], 16, %2;"
                 :: "r"(sdst), "l"(gsrc), "r"(nbytes));
}

__device__ __forceinline__ void ldsm4(uint32_t r[4], uint32_t addr){
    asm volatile("ldmatrix.sync.aligned.m8n8.x4.shared.b16 {%0,%1,%2,%3}, [%4];"
        : "=r"(r[0]), "=r"(r[1]), "=r"(r[2]), "=r"(r[3]) : "r"(addr));
}

// ---------------- k_hmma: 8-warp 2x4 GEMM, optional split-K ----------------
// mode 0: C = acc ; 2: softplus(acc+bias) ; 4: partial write to C + z*M*ldc.
template<int MT>
__global__ void __launch_bounds__(256, 2) k_hmma(
    const __half* __restrict__ A, int lda,
    const __half* __restrict__ B, int ldb,
    float* __restrict__ C, int ldc,
    int M, int N, int K, int KS,
    int mode, const float* __restrict__ bias)
{
    constexpr int BM = MT*32;
    extern __shared__ __half smh[];
    __half* As = smh;
    __half* Bs = smh + NSTG*BM*SROW;

    const int tid  = threadIdx.x;
    const int wid  = tid >> 5, lane = tid & 31;
    const int g    = lane >> 2, tg = lane & 3;
    const int wm   = (wid >> 2) * (MT*16);
    const int wn   = (wid & 3) * 32;
    const int bm   = blockIdx.y * BM;
    const int bn   = blockIdx.x * 128;
    const int lrow = tid >> 3;
    const int lcol = (tid & 7) * 8;
    const int k0   = blockIdx.z * KS;
    const int nch  = (((K - k0) < KS ? (K - k0) : KS)) >> 6;
    if (mode == 4) C += (size_t)blockIdx.z * (size_t)M * ldc;

    const uint32_t sA = (uint32_t)__cvta_generic_to_shared(As);
    const uint32_t sB = (uint32_t)__cvta_generic_to_shared(Bs);

    uint32_t aaddr[MT], baddr[2];
    {
        int arow = wm + (lane & 15);
        int acol = ((lane >> 4) & 1) * 8;
        #pragma unroll
        for (int mt = 0; mt < MT; mt++)
            aaddr[mt] = sA + (uint32_t)(((arow + mt*16)*SROW + acol)*2);
        #pragma unroll
        for (int ntp = 0; ntp < 2; ntp++){
            int brow = wn + ntp*16 + (lane & 7) + ((lane >> 4) & 1)*8;
            int bcol = ((lane >> 3) & 1) * 8;
            baddr[ntp] = sB + (uint32_t)((brow*SROW + bcol)*2);
        }
    }

    float acc[MT][4][4];
    #pragma unroll
    for (int mt = 0; mt < MT; mt++)
        #pragma unroll
        for (int nt = 0; nt < 4; nt++)
            #pragma unroll
            for (int i = 0; i < 4; i++) acc[mt][nt][i] = 0.f;

    auto issue = [&](int c){
        const int gk = k0 + c*64 + lcol;
        const int s  = c % NSTG;
        uint32_t da = sA + (uint32_t)((s*BM*SROW + lrow*SROW + lcol)*2);
        #pragma unroll
        for (int p = 0; p < BM/32; p++)
            cpa16(da + (uint32_t)(p*32*SROW*2),
                  A + (size_t)(bm + lrow + p*32)*lda + gk, 16);
        uint32_t db = sB + (uint32_t)((s*128*SROW + lrow*SROW + lcol)*2);
        #pragma unroll
        for (int p = 0; p < 4; p++){
            int gn = bn + lrow + p*32;
            cpa16(db + (uint32_t)(p*32*SROW*2),
                  B + (size_t)(gn < N ? gn : 0)*ldb + gk, (gn < N) ? 16 : 0);
        }
        asm volatile("cp.async.commit_group;");
    };

    issue(0);
    issue(1);
    for (int c = 0; c < nch; c++){
        if (c + 1 < nch) asm volatile("cp.async.wait_group 1;");
        else             asm volatile("cp.async.wait_group 0;");
        __syncthreads();
        if (c + 2 < nch) issue(c + 2);

        const uint32_t offA = (uint32_t)((c % NSTG)*BM*SROW*2);
        const uint32_t offB = (uint32_t)((c % NSTG)*128*SROW*2);
        #pragma unroll
        for (int kst = 0; kst < 4; kst++){
            uint32_t af[MT][4], bfr[2][4];
            #pragma unroll
            for (int mt = 0; mt < MT; mt++)
                ldsm4(af[mt], aaddr[mt] + offA + kst*32);
            #pragma unroll
            for (int ntp = 0; ntp < 2; ntp++)
                ldsm4(bfr[ntp], baddr[ntp] + offB + kst*32);
            #pragma unroll
            for (int mt = 0; mt < MT; mt++)
                #pragma unroll
                for (int nt = 0; nt < 4; nt++)
                    mma_f16(acc[mt][nt],
                            af[mt][0], af[mt][1], af[mt][2], af[mt][3],
                            bfr[nt >> 1][(nt & 1)*2], bfr[nt >> 1][(nt & 1)*2 + 1]);
        }
    }

    // epilogue: paired float2 stores (cols cl, cl+1 adjacent); bias reads bounds-guarded
    #pragma unroll
    for (int mt = 0; mt < MT; mt++){
        int r0 = bm + wm + mt*16 + g;
        #pragma unroll
        for (int nt = 0; nt < 4; nt++){
            int cl = bn + wn + nt*8 + 2*tg;
            #pragma unroll
            for (int half = 0; half < 2; half++){
                int rr = r0 + half*8;
                float v0 = acc[mt][nt][half*2 + 0];
                float v1 = acc[mt][nt][half*2 + 1];
                if (mode == 2){
                    float b0 = (cl     < N) ? bias[cl]     : 0.f;
                    float b1 = (cl + 1 < N) ? bias[cl + 1] : 0.f;
                    float x0 = v0 + b0, x1 = v1 + b1;
                    v0 = fmaxf(x0, 0.f) + log1pf(expf(-fabsf(x0)));
                    v1 = fmaxf(x1, 0.f) + log1pf(expf(-fabsf(x1)));
                }
                size_t idx = (size_t)rr*ldc + cl;
                if (cl + 1 < N){
                    *(float2*)(C + idx) = make_float2(v0, v1);
                } else if (cl < N){
                    C[idx] = v0;
                }
            }
        }
    }
}

#define SMEMH4 (NSTG*(128+128)*SROW*sizeof(__half))   // 110592
#define SMEMH2 (NSTG*(64 +128)*SROW*sizeof(__half))   // 82944

// ---------------- fused split-K reduce ----------------
__global__ void k_reddbc(){
    int i = blockIdx.x*blockDim.x + threadIdx.x;
    if (i >= NR*DBCN) return;
    int r = i / DBCN, c = i % DBCN;
    float s = 0.f;
    #pragma unroll
    for (int z = 0; z < SPL_DBC; z++)
        s += g_split[(size_t)z*NR*DBCP + (size_t)r*DBCP + c];
    g_dbc[(size_t)r*DBCP + c] = s;
    if (c < DTR) h_dbc[(size_t)r*DTKP + c] = __float2half(s);
}

// fused: h += sum of SPL_OUT partials, then rmsnorm(h, w) -> h_xn
__global__ void k_redout_norm(const float* __restrict__ w){
    __shared__ float sh[33];
    int n = blockIdx.x;
    float ss = 0.f;
    for (int d = threadIdx.x; d < DM; d += blockDim.x){
        size_t idx = (size_t)n*DM + d;
        float v = g_h[idx];
        #pragma unroll
        for (int z = 0; z < SPL_OUT; z++)
            v += g_split[(size_t)z*NR*DM + idx];
        g_h[idx] = v;
        ss += v*v;
    }
    for (int o = 16; o; o >>= 1) ss += __shfl_down_sync(0xffffffffu, ss, o);
    if ((threadIdx.x & 31) == 0) sh[threadIdx.x >> 5] = ss;
    __syncthreads();
    if (threadIdx.x < 32){
        float v = (threadIdx.x < (int)(blockDim.x >> 5)) ? sh[threadIdx.x] : 0.f;
        for (int o = 16; o; o >>= 1) v += __shfl_down_sync(0xffffffffu, v, o);
        if (threadIdx.x == 0) sh[32] = rsqrtf(v / (float)DM + EPSF);
    }
    __syncthreads();
    float sc = sh[32];
    for (int d = threadIdx.x; d < DM; d += blockDim.x)
        h_xn[(size_t)n*DMP + d] = __float2half(g_h[(size_t)n*DM + d] * sc * w[d]);
}

// fused: logits = sum of SPL_LM partials + per-block sum/sumsq
__global__ void k_redlm_red1(){
    __shared__ float s1[32], s2[32];
    int base = blockIdx.x * 1024;
    float s = 0.f, q = 0.f;
    for (int i = threadIdx.x; i < 1024; i += 256){
        float v = 0.f;
        #pragma unroll
        for (int z = 0; z < SPL_LM; z++)
            v += g_split[(size_t)z*NR*VOC + base + i];
        g_logit[base + i] = v;
        s += v; q += v*v;
    }
    for (int o = 16; o; o >>= 1){
        s += __shfl_down_sync(0xffffffffu, s, o);
        q += __shfl_down_sync(0xffffffffu, q, o);
    }
    if ((threadIdx.x & 31) == 0){ s1[threadIdx.x>>5] = s; s2[threadIdx.x>>5] = q; }
    __syncthreads();
    if (threadIdx.x < 32){
        float a = (threadIdx.x < 8) ? s1[threadIdx.x] : 0.f;
        float c = (threadIdx.x < 8) ? s2[threadIdx.x] : 0.f;
        for (int o = 4; o; o >>= 1){
            a += __shfl_down_sync(0xffffffffu, a, o);
            c += __shfl_down_sync(0xffffffffu, c, o);
        }
        if (threadIdx.x == 0){ g_part[blockIdx.x*2] = a; g_part[blockIdx.x*2+1] = c; }
    }
}

// final stats + wesum (single block)
__global__ void k_red2_wesum(const float* __restrict__ emb_w){
    __shared__ float s1[32], s2[32];
    float s = 0.f, q = 0.f;
    for (int i = threadIdx.x; i < 192; i += 256){ s += g_part[i*2]; q += g_part[i*2+1]; }
    for (int o = 16; o; o >>= 1){
        s += __shfl_down_sync(0xffffffffu, s, o);
        q += __shfl_down_sync(0xffffffffu, q, o);
    }
    if ((threadIdx.x & 31) == 0){ s1[threadIdx.x>>5] = s; s2[threadIdx.x>>5] = q; }
    __syncthreads();
    if (threadIdx.x == 0){
        float a = 0.f, c = 0.f;
        for (int i = 0; i < 8; i++){ a += s1[i]; c += s2[i]; }
        const float T = (float)(NR*VOC);
        float mean = a / T;
        float var  = c / T - mean*mean;
        g_stats[0] = mean;
        g_stats[1] = rsqrtf(var + EPSF);
    }
    float ws = 0.f;
    for (int v = 0; v < VOC; v++) ws += emb_w[threadIdx.x*VOC + v];
    g_wesum[threadIdx.x] = ws;
}

// ---------------- vectorized fp32 -> padded fp16 (unrolled) ----------------
__global__ void k_cvt2(const float* __restrict__ src, __half* __restrict__ dst,
                       int K, int KP){
    int r = blockIdx.x;
    const float2* s = (const float2*)(src + (size_t)r*K);
    __half* d = dst + (size_t)r*KP;
    const int n2 = K >> 1;
    #pragma unroll 4
    for (int i = threadIdx.x; i < n2; i += blockDim.x){
        float2 v = s[i];
        *(__half2*)(d + 2*i) = __floats2half2_rn(v.x, v.y);
    }
}

// merged: dt_w pad-convert (blocks [0, nb_dt)) + negA (blocks >= nb_dt)
__global__ void k_cvtw_negA(const float* __restrict__ dt_w, const float* __restrict__ Alog,
                            int nb_dt){
    if ((int)blockIdx.x < nb_dt){
        int i = blockIdx.x*blockDim.x + threadIdx.x;
        if (i < 2*ED*DTR)
            h_dtw[(size_t)(i/DTR)*DTKP + (i%DTR)] = __float2half(dt_w[i]);
    } else {
        int i = (blockIdx.x - nb_dt)*blockDim.x + threadIdx.x;
        if (i < 2*ED*DS) g_negA[i] = -expf(Alog[i]);
    }
}

// ---------------- fused input transpose + rmsnorm(layer0) ----------------
__global__ void k_trans_norm(const float* __restrict__ x, const float* __restrict__ w){
    __shared__ float sm[DM];
    __shared__ float sh[33];
    int n = blockIdx.x;
    const float* row = x + (size_t)n*DM;
    float ss = 0.f;
    for (int d = threadIdx.x; d < DM; d += blockDim.x){
        float v = row[d];
        sm[d] = v;
        ss += v*v;
    }
    for (int o = 16; o; o >>= 1) ss += __shfl_down_sync(0xffffffffu, ss, o);
    if ((threadIdx.x & 31) == 0) sh[threadIdx.x >> 5] = ss;
    __syncthreads();
    if (threadIdx.x < 32){
        float v = (threadIdx.x < (int)(blockDim.x >> 5)) ? sh[threadIdx.x] : 0.f;
        for (int o = 16; o; o >>= 1) v += __shfl_down_sync(0xffffffffu, v, o);
        if (threadIdx.x == 0) sh[32] = rsqrtf(v / (float)DM + EPSF);
    }
    __syncthreads();
    float sc = sh[32];
    for (int d = threadIdx.x; d < DM; d += blockDim.x){
        int c = d / 25, r = d % 25, f = r / 5, e = r % 5;
        float v = sm[(f*62 + c)*5 + e];
        g_h[(size_t)n*DM + d] = v;
        h_xn[(size_t)n*DMP + d] = __float2half(v * sc * w[d]);
    }
}

// ---------------- depthwise causal conv + silu -> fp16 xct only ----------------
__global__ void k_conv_silu(const float* __restrict__ cw, const float* __restrict__ cb){
    int e = blockIdx.x*blockDim.x + threadIdx.x;
    int b = blockIdx.y;
    if (e >= ED) return;
    size_t r0 = (size_t)(b*SEQ + 0)*(2*ED);
    size_t r1 = (size_t)(b*SEQ + 1)*(2*ED);
    size_t r2 = (size_t)(b*SEQ + 2)*(2*ED);
    float x0 = g_xz[r0 + e], x1 = g_xz[r1 + e], x2 = g_xz[r2 + e];
    float w1 = cw[e*4+1], w2 = cw[e*4+2], w3 = cw[e*4+3];
    float bb = cb[e];
    h_xct[(size_t)(b*SEQ + 0)*EDP + e] = __float2half(siluf(bb + w3*x0));
    h_xct[(size_t)(b*SEQ + 1)*EDP + e] = __float2half(siluf(bb + w2*x0 + w3*x1));
    h_xct[(size_t)(b*SEQ + 2)*EDP + e] = __float2half(siluf(bb + w1*x0 + w2*x1 + w3*x2));
}

// ---------------- fused SSM scan (recomputes conv+silu in fp32) ----------------
#define SCAN_BB 16
__global__ void k_scan(const float* __restrict__ nAbase, const float* __restrict__ Dp,
                       const float* __restrict__ cw, const float* __restrict__ cb){
    __shared__ float sB[SEQ][DS], sC[SEQ][DS];
    int e = blockIdx.x*blockDim.x + threadIdx.x;
    int t = threadIdx.x;
    bool act = (e < ED);

    float nA[DS], dpe = 0.f, w1 = 0.f, w2 = 0.f, w3 = 0.f, bb = 0.f;
    if (act){
        #pragma unroll
        for (int n = 0; n < DS; n++) nA[n] = nAbase[e*DS + n];
        dpe = Dp[e];
        w1 = cw[e*4+1]; w2 = cw[e*4+2]; w3 = cw[e*4+3]; bb = cb[e];
    }

    for (int bb_i = 0; bb_i < SCAN_BB; bb_i++){
        int b = blockIdx.y*SCAN_BB + bb_i;
        if (t < SEQ*DS){
            int s = t / DS, n = t % DS;
            size_t base = (size_t)(b*SEQ + s)*DBCP + DTR;
            sB[s][n] = g_dbc[base + n];
            sC[s][n] = g_dbc[base + DS + n];
        }
        __syncthreads();
        if (act){
            size_t r0 = (size_t)(b*SEQ + 0)*(2*ED);
            size_t r1 = (size_t)(b*SEQ + 1)*(2*ED);
            size_t r2 = (size_t)(b*SEQ + 2)*(2*ED);
            float x0 = g_xz[r0 + e], x1 = g_xz[r1 + e], x2 = g_xz[r2 + e];
            float xcv_s[SEQ];
            xcv_s[0] = siluf(bb + w3*x0);
            xcv_s[1] = siluf(bb + w2*x0 + w3*x1);
            xcv_s[2] = siluf(bb + w1*x0 + w2*x1 + w3*x2);

            float hst[DS];
            #pragma unroll
            for (int n = 0; n < DS; n++) hst[n] = 0.f;
            #pragma unroll
            for (int s = 0; s < SEQ; s++){
                size_t row = (size_t)(b*SEQ + s);
                float d   = g_delta[row*ED + e];
                float xcv = xcv_s[s];
                float dx  = d * xcv;
                float y = 0.f;
                #pragma unroll
                for (int n = 0; n < DS; n++){
                    float dA = __expf(d * nA[n]);
                    hst[n] = dA*hst[n] + dx*sB[s][n];
                    y = fmaf(hst[n], sC[s][n], y);
                }
                y += dpe * xcv;
                float z = g_xz[row*(2*ED) + ED + e];
                h_ys[row*EDP + e] = __float2half(y * siluf(z));
            }
        }
        __syncthreads();
    }
}

__global__ void k_nrm(){
    int i = blockIdx.x*blockDim.x + threadIdx.x;
    if (i < NR*VOC) h_nrm[i] = __float2half((g_logit[i] - g_stats[0]) * g_stats[1]);
}

// ---------------- final expand over f ----------------
__global__ void k_final(const float* __restrict__ bnw, const float* __restrict__ bnb,
                        const float* __restrict__ embb, float* __restrict__ out){
    int i = blockIdx.x*blockDim.x + threadIdx.x;
    const int total = BSZ*5*SEQ*OE;
    if (i >= total) return;
    int o = i & 255;
    int s = (i >> 8) % SEQ;
    int f = (i / (OE*SEQ)) % 5;
    int b = i / (OE*SEQ*5);
    int n = b*SEQ + s;
    out[i] = bnw[f]*g_t[(size_t)n*OE + o] + bnb[f]*g_wesum[o] + embb[o];
}

// ---------------- launch ----------------
extern "C" void kernel_launch(void* const* d_in, const int* in_sizes, int n_in,
                              void* d_out, int out_size)
{
    const float* x        = (const float*)d_in[0];
    const float* in_w     = (const float*)d_in[1];
    const float* conv_w   = (const float*)d_in[2];
    const float* conv_b   = (const float*)d_in[3];
    const float* xp_w     = (const float*)d_in[4];
    const float* dt_w     = (const float*)d_in[5];
    const float* dt_b     = (const float*)d_in[6];
    const float* A_log    = (const float*)d_in[7];
    const float* D_param  = (const float*)d_in[8];
    const float* out_w    = (const float*)d_in[9];
    const float* norm_w   = (const float*)d_in[10];
    const float* normf_w  = (const float*)d_in[11];
    const float* lm_w     = (const float*)d_in[12];
    const float* bn_w     = (const float*)d_in[13];
    const float* bn_b     = (const float*)d_in[14];
    const float* emb_w    = (const float*)d_in[15];
    const float* emb_b    = (const float*)d_in[16];
    float* out = (float*)d_out;

    cudaFuncSetAttribute(k_hmma<4>, cudaFuncAttributeMaxDynamicSharedMemorySize, (int)SMEMH4);
    cudaFuncSetAttribute(k_hmma<2>, cudaFuncAttributeMaxDynamicSharedMemorySize, (int)SMEMH2);

    float *pxz, *pdelta, *plog, *pt, *pnegA, *psplit;
    __half *qxn, *qinw, *qxct, *qxpw, *qdbc, *qdtw, *qys, *qoutw, *qlmw, *qnrm, *qembw;
    cudaGetSymbolAddress((void**)&pxz,    g_xz);
    cudaGetSymbolAddress((void**)&pdelta, g_delta);
    cudaGetSymbolAddress((void**)&plog,   g_logit);
    cudaGetSymbolAddress((void**)&pt,     g_t);
    cudaGetSymbolAddress((void**)&pnegA,  g_negA);
    cudaGetSymbolAddress((void**)&psplit, g_split);
    cudaGetSymbolAddress((void**)&qxn,    h_xn);
    cudaGetSymbolAddress((void**)&qinw,   h_inw);
    cudaGetSymbolAddress((void**)&qxct,   h_xct);
    cudaGetSymbolAddress((void**)&qxpw,   h_xpw);
    cudaGetSymbolAddress((void**)&qdbc,   h_dbc);
    cudaGetSymbolAddress((void**)&qdtw,   h_dtw);
    cudaGetSymbolAddress((void**)&qys,    h_ys);
    cudaGetSymbolAddress((void**)&qoutw,  h_outw);
    cudaGetSymbolAddress((void**)&qlmw,   h_lmw);
    cudaGetSymbolAddress((void**)&qnrm,   h_nrm);
    cudaGetSymbolAddress((void**)&qembw,  h_embw);

    // launches 0..3: profiled launch (index 3) = in_proj GEMM (control)
    k_trans_norm<<<NR, 256>>>(x, norm_w);                                   // 0
    k_cvt2<<<2*2*ED, 256>>>(in_w, qinw, DM, DMP);                           // 1
    k_cvt2<<<2*DM, 256>>>(out_w, qoutw, ED, EDP);                           // 2
    k_hmma<4><<<dim3(49, 12), 256, SMEMH4>>>(                               // 3 <- profiled
        qxn, DMP, qinw, DMP, pxz, 2*ED, NR, 2*ED, DMP, DMP, 0, nullptr);

    // remaining weight conversions (merged)
    k_cvt2<<<2*DBCN, 256>>>(xp_w, qxpw, ED, EDP);
    {
        int nb_dt = (2*ED*DTR + 255)/256;
        int nb_na = (2*ED*DS + 255)/256;
        k_cvtw_negA<<<nb_dt + nb_na, 256>>>(dt_w, A_log, nb_dt);
    }

    for (int l = 0; l < 2; l++){
        if (l == 1){
            k_hmma<4><<<dim3(49, 12), 256, SMEMH4>>>(
                qxn, DMP, qinw + (size_t)2*ED*DMP, DMP, pxz, 2*ED, NR, 2*ED, DMP, DMP, 0, nullptr);
        }
        k_conv_silu<<<dim3((ED+255)/256, BSZ), 256>>>(conv_w + (size_t)l*ED*4, conv_b + l*ED);
        // dbc partials: xct @ xp_w^T  (1536 x 129, K=3136, split-K 6 x 576)
        k_hmma<2><<<dim3(2, 24, SPL_DBC), 256, SMEMH2>>>(
            qxct, EDP, qxpw + (size_t)l*DBCN*EDP, EDP, psplit, DBCP, NR, DBCN, EDP, KS_DBC, 4, nullptr);
        k_reddbc<<<(NR*DBCN + 255)/256, 256>>>();
        // delta = softplus(dt @ dtw^T + dt_b)  (1536 x 3100, K=128)
        k_hmma<4><<<dim3(25, 12), 256, SMEMH4>>>(
            qdbc, DTKP, qdtw + (size_t)l*ED*DTKP, DTKP, pdelta, ED, NR, ED, DTKP, DTKP, 2, dt_b + l*ED);
        // scan (recomputes conv inline) -> h_ys
        k_scan<<<dim3((ED+255)/256, BSZ/SCAN_BB), 256>>>(
            pnegA + (size_t)l*ED*DS, D_param + l*ED, conv_w + (size_t)l*ED*4, conv_b + l*ED);
        // out_proj partials (split-K 4 x 832)
        k_hmma<4><<<dim3(13, 12, SPL_OUT), 256, SMEMH4>>>(
            qys, EDP, qoutw + (size_t)l*DM*EDP, EDP, psplit, DM, NR, DM, EDP, KS_OUT, 4, nullptr);
        // fused: h += partials, rmsnorm -> h_xn
        k_redout_norm<<<NR, 256>>>(l == 0 ? norm_w + DM : normf_w);
    }

    k_cvt2<<<VOC, 256>>>(lm_w, qlmw, DM, DMP);
    // logits partials (split-K 5 x 320)
    k_hmma<2><<<dim3(1, 24, SPL_LM), 256, SMEMH2>>>(
        qxn, DMP, qlmw, DMP, psplit, VOC, NR, VOC, DMP, KS_LM, 4, nullptr);
    k_redlm_red1<<<192, 256>>>();
    k_red2_wesum<<<1, 256>>>(emb_w);
    k_nrm<<<(NR*VOC + 255)/256, 256>>>();
    k_cvt2<<<OE, 256>>>(emb_w, qembw, VOC, VOC);
    // t = nrm @ emb_w^T  (1536 x 256, K=128)
    k_hmma<2><<<dim3(2, 24), 256, SMEMH2>>>(
        qnrm, VOC, qembw, VOC, pt, OE, NR, OE, VOC, VOC, 0, nullptr);
    k_final<<<(BSZ*5*SEQ*OE + 255)/256, 256>>>(bn_w, bn_b, emb_b, out);
}